// round 12
// baseline (speedup 1.0000x reference)
#include <cuda_runtime.h>
#include <cuda_bf16.h>
#include <math.h>

// Problem constants
#define BB   8
#define DIM  128
#define HH   64
#define WW   64
#define HW   4096
#define KK   7
#define GG   8
#define GC   16
#define C1   32
#define C2   392
#define NPIX 32768

// -------- scratch (device globals) --------
__device__ float    g_t[BB * C1 * HW];        // conv1+bn+relu, NCHW fp32 (4 MB)
__device__ float    g_y[NPIX * DIM];          // involution out, NHWC fp32 (17 MB)
__device__ unsigned g_hb[NPIX * 128];         // pw1+gelu out, bf16 k-pairs, [px][f/2] (16 MB)

// -------- helpers --------
__device__ __forceinline__ unsigned packbf(float lo, float hi) {
    unsigned r; asm("cvt.rn.bf16x2.f32 %0, %1, %2;" : "=r"(r) : "f"(hi), "f"(lo)); return r;
}
__device__ __forceinline__ void mma16(float* c, unsigned a0, unsigned a1,
                                      unsigned a2, unsigned a3,
                                      unsigned b0, unsigned b1) {
    asm volatile(
        "mma.sync.aligned.m16n8k16.row.col.f32.bf16.bf16.f32 "
        "{%0,%1,%2,%3}, {%4,%5,%6,%7}, {%8,%9}, {%0,%1,%2,%3};\n"
        : "+f"(c[0]), "+f"(c[1]), "+f"(c[2]), "+f"(c[3])
        : "r"(a0), "r"(a1), "r"(a2), "r"(a3), "r"(b0), "r"(b1));
}
__device__ __forceinline__ void ldsm4(unsigned& r0, unsigned& r1,
                                      unsigned& r2, unsigned& r3, unsigned addr) {
    asm volatile("ldmatrix.sync.aligned.m8n8.x4.shared.b16 {%0,%1,%2,%3}, [%4];\n"
        : "=r"(r0), "=r"(r1), "=r"(r2), "=r"(r3) : "r"(addr));
}
// tanh-form GELU (validated: rel_err unchanged at 1.79e-4)
__device__ __forceinline__ float gelu_fast(float z) {
    float u = z * (0.7978845608f + 0.0356774081f * z * z);
    float e = __expf(-2.f * u);
    return __fdividef(z, 1.f + e);
}

// Row stride for ldmatrix operand tiles: 64 k-pairs + 4 pad = 68 u32 = 272 B.
#define RS 68
#define RSB 272

// =====================================================================
// K1: t = relu(bn(conv1(x)))  — bf16 MMA, M=32, N=128px, K=128
// =====================================================================
__global__ __launch_bounds__(256) void k1_conv1(
    const float* __restrict__ x,  const float* __restrict__ w1,
    const float* __restrict__ b1, const float* __restrict__ bng,
    const float* __restrict__ bnb, const float* __restrict__ bnm,
    const float* __restrict__ bnv) {
    extern __shared__ unsigned smu[];
    unsigned* wAu = smu;                 // 32*68
    unsigned* xsu = smu + 32 * 68;       // 64*136
    float* bs = (float*)(xsu + 64 * 136);
    float* ss = bs + 32;
    int tid = threadIdx.x;

    if (tid < 32) {
        float sc = bng[tid] * rsqrtf(bnv[tid] + 1e-5f);
        ss[tid] = sc;
        bs[tid] = b1[tid] * sc + bnb[tid] - bnm[tid] * sc;
    }
    __syncthreads();
    for (int i = tid; i < 32 * 64; i += 256) {
        int o = i >> 6, c2 = i & 63;
        float sc = ss[o];
        wAu[o * 68 + c2] = packbf(w1[o * 128 + 2 * c2] * sc, w1[o * 128 + 2 * c2 + 1] * sc);
    }
    int pb = blockIdx.x * 128, b = pb >> 12, pin = pb & 4095;
    const float* xb = x + b * DIM * HW + pin;
    for (int i = tid; i < 64 * 128; i += 256) {
        int c2 = i >> 7, p = i & 127;
        xsu[c2 * 136 + p] = packbf(xb[(2 * c2) * HW + p], xb[(2 * c2 + 1) * HW + p]);
    }
    __syncthreads();

    int wid = tid >> 5, lane = tid & 31, gid = lane >> 2, ctid = lane & 3;
    int m = wid & 1, ng = wid >> 1;
    int px0 = ng * 32;
    float acc[4][4];
#pragma unroll
    for (int a = 0; a < 4; a++)
#pragma unroll
        for (int q = 0; q < 4; q++) acc[a][q] = 0.f;

#pragma unroll
    for (int s = 0; s < 8; s++) {
        const unsigned* ap = wAu + (m * 16 + gid) * 68 + s * 8 + ctid;
        unsigned a0 = ap[0], a1 = ap[8 * 68], a2 = ap[4], a3 = ap[8 * 68 + 4];
#pragma unroll
        for (int nt = 0; nt < 4; nt++) {
            int pxn = px0 + nt * 8 + gid;
            unsigned b0 = xsu[(s * 8 + ctid) * 136 + pxn];
            unsigned b1v = xsu[(s * 8 + ctid + 4) * 136 + pxn];
            mma16(acc[nt], a0, a1, a2, a3, b0, b1v);
        }
    }
    float* tb = g_t + b * C1 * HW + pin;
    int o0 = m * 16 + gid;
#pragma unroll
    for (int nt = 0; nt < 4; nt++) {
        int px = px0 + nt * 8 + 2 * ctid;
        float b0v = bs[o0], b1v = bs[o0 + 8];
        *(float2*)(tb + o0 * HW + px) =
            make_float2(fmaxf(acc[nt][0] + b0v, 0.f), fmaxf(acc[nt][1] + b0v, 0.f));
        *(float2*)(tb + (o0 + 8) * HW + px) =
            make_float2(fmaxf(acc[nt][2] + b1v, 0.f), fmaxf(acc[nt][3] + b1v, 0.f));
    }
}

// =====================================================================
// K23: fused conv2 + involution — 512 threads (16 warps, 1 CTA/SM).
// Phases: stage t/w/bias → sync → MMA (4m×4n warps) → sync →
//         predicated x-halo fill → sync → stencil (4gc×4px / thread).
// smem: wgt 49*520 f | tsu 16*520 u | wAu 64*20 u | bsm 64 f | xs 16128 f
// =====================================================================
#define XS_ROW 72
#define XS_CH  (14 * 72)
#define WGT_S  520
__global__ __launch_bounds__(512) void k23_conv2_inv(
    const float* __restrict__ x, const float* __restrict__ w2,
    const float* __restrict__ b2) {
    extern __shared__ float smf[];
    float* wgt = smf;                          // 49*520
    unsigned* tsu = (unsigned*)(smf + 49 * WGT_S);   // 16*520
    unsigned* wAu = tsu + 16 * WGT_S;          // 64*20
    float* bsm = (float*)(wAu + 64 * 20);      // 64
    float* xs  = bsm + 64;                     // 16*14*72
    int tid = threadIdx.x;
    int h0 = blockIdx.x * 8;
    int g  = blockIdx.y;
    int b  = blockIdx.z;

    // ---- stage t-tile, conv2 weights, bias ----
    const float* tb = g_t + b * C1 * HW + h0 * 64;
    for (int i = tid; i < 16 * 512; i += 512) {
        int c2 = i >> 9, px = i & 511;
        tsu[c2 * WGT_S + px] = packbf(tb[(2 * c2) * HW + px], tb[(2 * c2 + 1) * HW + px]);
    }
    for (int i = tid; i < 64 * 16; i += 512) {
        int o = i >> 4, c2 = i & 15;
        float a0 = 0.f, a1 = 0.f;
        if (o < 49) {
            int go = g * 49 + o;
            a0 = w2[go * C1 + 2 * c2];
            a1 = w2[go * C1 + 2 * c2 + 1];
        }
        wAu[o * 20 + c2] = packbf(a0, a1);
    }
    if (tid < 64) bsm[tid] = (tid < 49) ? b2[g * 49 + tid] : 0.f;
    __syncthreads();

    // ---- Phase A MMA: M=64(49), N=512, K=32; 16 warps = 4m × 4n ----
    {
        int wid = tid >> 5, lane = tid & 31, gid = lane >> 2, ctid = lane & 3;
        int m = wid & 3, ng = wid >> 2;
        int orow = m * 16 + gid;
        float bb0 = bsm[orow], bb1 = bsm[orow + 8];
        float acc[16][4];
#pragma unroll
        for (int nt = 0; nt < 16; nt++)
#pragma unroll
            for (int q = 0; q < 4; q++) acc[nt][q] = 0.f;
#pragma unroll
        for (int s = 0; s < 2; s++) {
            const unsigned* ap = wAu + orow * 20 + s * 8 + ctid;
            unsigned a0 = ap[0], a1 = ap[8 * 20], a2 = ap[4], a3 = ap[8 * 20 + 4];
#pragma unroll
            for (int nt = 0; nt < 16; nt++) {
                int pxn = ng * 128 + nt * 8 + gid;
                unsigned b0 = tsu[(s * 8 + ctid) * WGT_S + pxn];
                unsigned b1v = tsu[(s * 8 + ctid + 4) * WGT_S + pxn];
                mma16(acc[nt], a0, a1, a2, a3, b0, b1v);
            }
        }
#pragma unroll
        for (int nt = 0; nt < 16; nt++) {
            int px = ng * 128 + nt * 8 + 2 * ctid;
            if (orow < 49)
                *(float2*)(wgt + orow * WGT_S + px) =
                    make_float2(acc[nt][0] + bb0, acc[nt][1] + bb0);
            if (orow + 8 < 49)
                *(float2*)(wgt + (orow + 8) * WGT_S + px) =
                    make_float2(acc[nt][2] + bb1, acc[nt][3] + bb1);
        }
    }
    __syncthreads();   // wgt complete; tsu dead

    // ---- single-pass predicated x-halo fill ----
    const float* xg = x + (b * DIM + g * GC) * HW;
    for (int idx = tid; idx < GC * 14 * XS_ROW; idx += 512) {
        int gc = idx / (14 * XS_ROW);
        int rem = idx - gc * (14 * XS_ROW);
        int rr = rem / XS_ROW;
        int cc = rem - rr * XS_ROW;
        int hh = h0 - 3 + rr;
        int ws = cc - 3;
        float v = 0.f;
        if (hh >= 0 && hh < HH && ws >= 0 && ws < WW)
            v = xg[gc * HW + hh * WW + ws];
        xs[idx] = v;
    }
    __syncthreads();

    // ---- stencil: thread = (4 gc, 4 px); 512 work units exactly ----
    int gcQ = tid & 3;                // 4 gc per thread
    int pxq = tid >> 2;               // 0..127
    int r = pxq >> 4, w0 = (pxq & 15) * 4;
    float acc[4][4];
#pragma unroll
    for (int gc4 = 0; gc4 < 4; gc4++)
#pragma unroll
        for (int l = 0; l < 4; l++) acc[gc4][l] = 0.f;

    const float* wp = wgt + r * 64 + w0;
#pragma unroll
    for (int i = 0; i < KK; i++) {
        float4 wv[KK];
#pragma unroll
        for (int j = 0; j < KK; j++)
            wv[j] = *(const float4*)(wp + (i * KK + j) * WGT_S);
#pragma unroll
        for (int gc4 = 0; gc4 < 4; gc4++) {
            int gc = gcQ * 4 + gc4;
            const float* xrow = xs + gc * XS_CH + (r + i) * XS_ROW + w0;
            float4 xa = *(const float4*)(xrow);
            float4 xb4 = *(const float4*)(xrow + 4);
            float4 xc = *(const float4*)(xrow + 8);
            float xw[12] = {xa.x, xa.y, xa.z, xa.w, xb4.x, xb4.y, xb4.z, xb4.w,
                            xc.x, xc.y, xc.z, xc.w};
#pragma unroll
            for (int j = 0; j < KK; j++) {
                acc[gc4][0] += wv[j].x * xw[j];
                acc[gc4][1] += wv[j].y * xw[j + 1];
                acc[gc4][2] += wv[j].z * xw[j + 2];
                acc[gc4][3] += wv[j].w * xw[j + 3];
            }
        }
    }
#pragma unroll
    for (int l = 0; l < 4; l++) {
        float* yo = g_y + (b * HW + (h0 + r) * WW + w0 + l) * DIM + g * GC + gcQ * 4;
        *(float4*)(yo) = make_float4(acc[0][l], acc[1][l], acc[2][l], acc[3][l]);
    }
}

// =====================================================================
// K4A: fused LN + pw1 + fast GELU — ldmatrix mainloop.
// M=128 f/block (of 256), N=128 px, K=128. grid (256,2), 256 thr, 2 CTAs/SM.
// =====================================================================
#define OT_S 130
__global__ __launch_bounds__(256, 2) void k4a_pw1(
    const float* __restrict__ p1w, const float* __restrict__ p1b,
    const float* __restrict__ lng_g, const float* __restrict__ lnb_g) {
    extern __shared__ unsigned smu[];
    unsigned* aT = smu;                        // 128*68 (weights, rows=f)
    unsigned* bT = smu + 128 * RS;             // 128*68 (LN(y), rows=px)
    float* b1s = (float*)(smu + 2 * 128 * RS); // 128
    float* lng = b1s + 128;                    // 128
    float* lnb = lng + 128;                    // 128
    float* outT = (float*)smu;                 // 128*130 (union)
    int tid = threadIdx.x;
    int f0 = blockIdx.y * 128;
    int pb = blockIdx.x * 128;

#pragma unroll
    for (int k = 0; k < 32; k++) {
        int i = tid + k * 256;
        int f = i >> 6, c2 = i & 63;
        float2 wv = *(const float2*)(p1w + (f0 + f) * 128 + 2 * c2);
        aT[f * RS + c2] = packbf(wv.x, wv.y);
    }
    if (tid < 128) {
        b1s[tid] = p1b[f0 + tid];
        lng[tid] = lng_g[tid];
        lnb[tid] = lnb_g[tid];
    }
    __syncthreads();   // lng/lnb visible

    // ---- fused LayerNorm: 2 threads / pixel, pack into bT ----
    {
        int p = tid >> 1, half = tid & 1;
        const float* yp = g_y + (pb + p) * DIM + half * 64;
        float4 v[16];
        float s = 0.f, q = 0.f;
#pragma unroll
        for (int i = 0; i < 16; i++) {
            v[i] = *(const float4*)(yp + i * 4);
            s += v[i].x + v[i].y + v[i].z + v[i].w;
            q += v[i].x*v[i].x + v[i].y*v[i].y + v[i].z*v[i].z + v[i].w*v[i].w;
        }
        s += __shfl_xor_sync(0xffffffffu, s, 1);
        q += __shfl_xor_sync(0xffffffffu, q, 1);
        float mu = s * (1.f / 128.f);
        float var = q * (1.f / 128.f) - mu * mu;
        float rs = rsqrtf(var + 1e-6f);
        unsigned* brow = bT + p * RS + half * 32;
#pragma unroll
        for (int i = 0; i < 16; i++) {
            int c = half * 64 + i * 4;
            float n0 = (v[i].x - mu) * rs * lng[c+0] + lnb[c+0];
            float n1 = (v[i].y - mu) * rs * lng[c+1] + lnb[c+1];
            float n2 = (v[i].z - mu) * rs * lng[c+2] + lnb[c+2];
            float n3 = (v[i].w - mu) * rs * lng[c+3] + lnb[c+3];
            brow[2 * i]     = packbf(n0, n1);
            brow[2 * i + 1] = packbf(n2, n3);
        }
    }
    __syncthreads();

    int wid = tid >> 5, lane = tid & 31;
    int m = wid & 3, ng = wid >> 2;
    unsigned aBase = (unsigned)__cvta_generic_to_shared(aT)
                   + (m * 32 + (lane & 15)) * RSB + (lane & 16);
    unsigned bBase = (unsigned)__cvta_generic_to_shared(bT)
                   + (ng * 64 + (lane & 7) + ((lane & 16) >> 1)) * RSB
                   + ((lane & 8) << 1);
    float acc[2][8][4];
#pragma unroll
    for (int mt = 0; mt < 2; mt++)
#pragma unroll
        for (int nt = 0; nt < 8; nt++)
#pragma unroll
            for (int q = 0; q < 4; q++) acc[mt][nt][q] = 0.f;

#pragma unroll
    for (int s = 0; s < 8; s++) {
        unsigned a[2][4];
#pragma unroll
        for (int mt = 0; mt < 2; mt++)
            ldsm4(a[mt][0], a[mt][1], a[mt][2], a[mt][3],
                  aBase + mt * 16 * RSB + s * 32);
#pragma unroll
        for (int ntp = 0; ntp < 4; ntp++) {
            unsigned b0, b1v, b2, b3;
            ldsm4(b0, b1v, b2, b3, bBase + ntp * 16 * RSB + s * 32);
#pragma unroll
            for (int mt = 0; mt < 2; mt++) {
                mma16(acc[mt][2 * ntp],     a[mt][0], a[mt][1], a[mt][2], a[mt][3], b0, b1v);
                mma16(acc[mt][2 * ntp + 1], a[mt][0], a[mt][1], a[mt][2], a[mt][3], b2, b3);
            }
        }
    }
    __syncthreads();   // operand buffers dead → outT

    int gid = lane >> 2, ctid = lane & 3;
#pragma unroll
    for (int mt = 0; mt < 2; mt++) {
        int frow = m * 32 + mt * 16 + gid;
        float bb0 = b1s[frow], bb1 = b1s[frow + 8];
#pragma unroll
        for (int nt = 0; nt < 8; nt++) {
            int px = ng * 64 + nt * 8 + 2 * ctid;
            *(float2*)(outT + frow * OT_S + px) =
                make_float2(gelu_fast(acc[mt][nt][0] + bb0), gelu_fast(acc[mt][nt][1] + bb0));
            *(float2*)(outT + (frow + 8) * OT_S + px) =
                make_float2(gelu_fast(acc[mt][nt][2] + bb1), gelu_fast(acc[mt][nt][3] + bb1));
        }
    }
    __syncthreads();

    // coalesced pack + store to g_hb [px][f/2]
    int fcol = f0 >> 1;
#pragma unroll
    for (int k = 0; k < 32; k++) {
        int i = tid + k * 256;
        int pxl = i >> 6, f2l = i & 63;
        float lo = outT[(2 * f2l) * OT_S + pxl];
        float hi = outT[(2 * f2l + 1) * OT_S + pxl];
        g_hb[(pb + pxl) * 128 + fcol + f2l] = packbf(lo, hi);
    }
}

// =====================================================================
// K4B: pw2 + bias + residual — ldmatrix mainloop. M=128 c, N=128 px,
// K=256 in 2 chunks. grid 256, block 256, 2 CTAs/SM.
// =====================================================================
__global__ __launch_bounds__(256, 2) void k4b_pw2(
    const float* __restrict__ p2w, const float* __restrict__ p2b,
    const float* __restrict__ x,   float* __restrict__ out) {
    extern __shared__ unsigned smu[];
    unsigned* aT = smu;                        // 128*68 (w2, rows=c)
    unsigned* bT = smu + 128 * RS;             // 128*68 (h, rows=px)
    float* b2s = (float*)(smu + 2 * 128 * RS); // 128
    float* outT = (float*)smu;                 // 128*130 (union)
    int tid = threadIdx.x;
    int pb = blockIdx.x * 128, b = pb >> 12, pin = pb & 4095;
    if (tid < 128) b2s[tid] = p2b[tid];

    int wid = tid >> 5, lane = tid & 31;
    int m = wid & 3, ng = wid >> 2;
    unsigned aBase = (unsigned)__cvta_generic_to_shared(aT)
                   + (m * 32 + (lane & 15)) * RSB + (lane & 16);
    unsigned bBase = (unsigned)__cvta_generic_to_shared(bT)
                   + (ng * 64 + (lane & 7) + ((lane & 16) >> 1)) * RSB
                   + ((lane & 8) << 1);
    float acc[2][8][4];
#pragma unroll
    for (int mt = 0; mt < 2; mt++)
#pragma unroll
        for (int nt = 0; nt < 8; nt++)
#pragma unroll
            for (int q = 0; q < 4; q++) acc[mt][nt][q] = 0.f;

    for (int kc = 0; kc < 2; kc++) {
        __syncthreads();
#pragma unroll
        for (int k = 0; k < 32; k++) {
            int i = tid + k * 256;
            int c = i >> 6, f2 = i & 63;
            float2 wv = *(const float2*)(p2w + c * 256 + kc * 128 + 2 * f2);
            aT[c * RS + f2] = packbf(wv.x, wv.y);
        }
#pragma unroll
        for (int k = 0; k < 32; k++) {
            int i = tid + k * 256;
            int p = i >> 6, f2 = i & 63;
            bT[p * RS + f2] = g_hb[(pb + p) * 128 + kc * 64 + f2];
        }
        __syncthreads();
#pragma unroll
        for (int s = 0; s < 8; s++) {
            unsigned a[2][4];
#pragma unroll
            for (int mt = 0; mt < 2; mt++)
                ldsm4(a[mt][0], a[mt][1], a[mt][2], a[mt][3],
                      aBase + mt * 16 * RSB + s * 32);
#pragma unroll
            for (int ntp = 0; ntp < 4; ntp++) {
                unsigned b0, b1v, b2v, b3;
                ldsm4(b0, b1v, b2v, b3, bBase + ntp * 16 * RSB + s * 32);
#pragma unroll
                for (int mt = 0; mt < 2; mt++) {
                    mma16(acc[mt][2 * ntp],     a[mt][0], a[mt][1], a[mt][2], a[mt][3], b0, b1v);
                    mma16(acc[mt][2 * ntp + 1], a[mt][0], a[mt][1], a[mt][2], a[mt][3], b2v, b3);
                }
            }
        }
    }
    __syncthreads();   // operand buffers dead → outT

    int gid = lane >> 2, ctid = lane & 3;
#pragma unroll
    for (int mt = 0; mt < 2; mt++) {
        int crow = m * 32 + mt * 16 + gid;
        float bb0 = b2s[crow], bb1 = b2s[crow + 8];
#pragma unroll
        for (int nt = 0; nt < 8; nt++) {
            int px = ng * 64 + nt * 8 + 2 * ctid;
            *(float2*)(outT + crow * OT_S + px) =
                make_float2(acc[mt][nt][0] + bb0, acc[mt][nt][1] + bb0);
            *(float2*)(outT + (crow + 8) * OT_S + px) =
                make_float2(acc[mt][nt][2] + bb1, acc[mt][nt][3] + bb1);
        }
    }
    __syncthreads();

    // coalesced residual + store (NCHW): 128 c × 64 px-pairs = 8192 float2
#pragma unroll
    for (int k = 0; k < 32; k++) {
        int i = tid + k * 256;
        int c = i >> 6, p2 = (i & 63) * 2;
        float2 v = *(const float2*)(outT + c * OT_S + p2);
        int base = (b * DIM + c) * HW + pin + p2;
        float2 xi = *(const float2*)(x + base);
        *(float2*)(out + base) = make_float2(v.x + xi.x, v.y + xi.y);
    }
}

// =====================================================================
extern "C" void kernel_launch(void* const* d_in, const int* in_sizes, int n_in,
                              void* d_out, int out_size) {
    const float* x    = (const float*)d_in[0];
    const float* c1w  = (const float*)d_in[1];
    const float* c1b  = (const float*)d_in[2];
    const float* bng  = (const float*)d_in[3];
    const float* bnb  = (const float*)d_in[4];
    const float* bnm  = (const float*)d_in[5];
    const float* bnv  = (const float*)d_in[6];
    const float* c2w  = (const float*)d_in[7];
    const float* c2b  = (const float*)d_in[8];
    const float* lng  = (const float*)d_in[9];
    const float* lnb  = (const float*)d_in[10];
    const float* p1w  = (const float*)d_in[11];
    const float* p1b  = (const float*)d_in[12];
    const float* p2w  = (const float*)d_in[13];
    const float* p2b  = (const float*)d_in[14];
    float* out = (float*)d_out;

    const int SM_K1  = (32 * 68 + 64 * 136 + 64) * 4;
    const int SM_K23 = (49 * WGT_S + 16 * WGT_S + 64 * 20 + 64 + GC * XS_CH) * 4;  // 205088
    const int SM_K4A = (2 * 128 * RS + 384) * 4;          // 71168 B
    const int SM_K4B = (2 * 128 * RS + 128) * 4;          // 70144 B

    cudaFuncSetAttribute(k1_conv1,      cudaFuncAttributeMaxDynamicSharedMemorySize, SM_K1);
    cudaFuncSetAttribute(k23_conv2_inv, cudaFuncAttributeMaxDynamicSharedMemorySize, SM_K23);
    cudaFuncSetAttribute(k4a_pw1,       cudaFuncAttributeMaxDynamicSharedMemorySize, SM_K4A);
    cudaFuncSetAttribute(k4b_pw2,       cudaFuncAttributeMaxDynamicSharedMemorySize, SM_K4B);

    k1_conv1<<<256, 256, SM_K1>>>(x, c1w, c1b, bng, bnb, bnm, bnv);
    k23_conv2_inv<<<dim3(8, 8, 8), 512, SM_K23>>>(x, c2w, c2b);
    k4a_pw1<<<dim3(256, 2), 256, SM_K4A>>>(p1w, p1b, lng, lnb);
    k4b_pw2<<<256, 256, SM_K4B>>>(p2w, p2b, x, out);
}

// round 13
// speedup vs baseline: 1.1253x; 1.1253x over previous
#include <cuda_runtime.h>
#include <cuda_bf16.h>
#include <math.h>

// Problem constants
#define BB   8
#define DIM  128
#define HH   64
#define WW   64
#define HW   4096
#define KK   7
#define GG   8
#define GC   16
#define C1   32
#define C2   392
#define NPIX 32768

// -------- scratch (device globals) --------
__device__ float    g_t[BB * C1 * HW];        // conv1+bn+relu, NCHW fp32 (4 MB)
__device__ float    g_y[NPIX * DIM];          // involution out, NHWC fp32 (17 MB)
__device__ unsigned g_hb[NPIX * 128];         // pw1+gelu out, bf16 k-pairs, [px][f/2] (16 MB)

// -------- helpers --------
__device__ __forceinline__ unsigned packbf(float lo, float hi) {
    unsigned r; asm("cvt.rn.bf16x2.f32 %0, %1, %2;" : "=r"(r) : "f"(hi), "f"(lo)); return r;
}
__device__ __forceinline__ void mma16(float* c, unsigned a0, unsigned a1,
                                      unsigned a2, unsigned a3,
                                      unsigned b0, unsigned b1) {
    asm volatile(
        "mma.sync.aligned.m16n8k16.row.col.f32.bf16.bf16.f32 "
        "{%0,%1,%2,%3}, {%4,%5,%6,%7}, {%8,%9}, {%0,%1,%2,%3};\n"
        : "+f"(c[0]), "+f"(c[1]), "+f"(c[2]), "+f"(c[3])
        : "r"(a0), "r"(a1), "r"(a2), "r"(a3), "r"(b0), "r"(b1));
}
__device__ __forceinline__ void ldsm4(unsigned& r0, unsigned& r1,
                                      unsigned& r2, unsigned& r3, unsigned addr) {
    asm volatile("ldmatrix.sync.aligned.m8n8.x4.shared.b16 {%0,%1,%2,%3}, [%4];\n"
        : "=r"(r0), "=r"(r1), "=r"(r2), "=r"(r3) : "r"(addr));
}
// tanh-form GELU (validated: rel_err unchanged at 1.79e-4)
__device__ __forceinline__ float gelu_fast(float z) {
    float u = z * (0.7978845608f + 0.0356774081f * z * z);
    float e = __expf(-2.f * u);
    return __fdividef(z, 1.f + e);
}

// Row stride for ldmatrix operand tiles: 64 k-pairs + 4 pad = 68 u32 = 272 B.
#define RS 68
#define RSB 272

// =====================================================================
// K1: t = relu(bn(conv1(x)))  — bf16 MMA, M=32, N=128px, K=128
// =====================================================================
__global__ __launch_bounds__(256) void k1_conv1(
    const float* __restrict__ x,  const float* __restrict__ w1,
    const float* __restrict__ b1, const float* __restrict__ bng,
    const float* __restrict__ bnb, const float* __restrict__ bnm,
    const float* __restrict__ bnv) {
    extern __shared__ unsigned smu[];
    unsigned* wAu = smu;                 // 32*68
    unsigned* xsu = smu + 32 * 68;       // 64*136
    float* bs = (float*)(xsu + 64 * 136);
    float* ss = bs + 32;
    int tid = threadIdx.x;

    if (tid < 32) {
        float sc = bng[tid] * rsqrtf(bnv[tid] + 1e-5f);
        ss[tid] = sc;
        bs[tid] = b1[tid] * sc + bnb[tid] - bnm[tid] * sc;
    }
    __syncthreads();
    for (int i = tid; i < 32 * 64; i += 256) {
        int o = i >> 6, c2 = i & 63;
        float sc = ss[o];
        wAu[o * 68 + c2] = packbf(w1[o * 128 + 2 * c2] * sc, w1[o * 128 + 2 * c2 + 1] * sc);
    }
    int pb = blockIdx.x * 128, b = pb >> 12, pin = pb & 4095;
    const float* xb = x + b * DIM * HW + pin;
    for (int i = tid; i < 64 * 128; i += 256) {
        int c2 = i >> 7, p = i & 127;
        xsu[c2 * 136 + p] = packbf(xb[(2 * c2) * HW + p], xb[(2 * c2 + 1) * HW + p]);
    }
    __syncthreads();

    int wid = tid >> 5, lane = tid & 31, gid = lane >> 2, ctid = lane & 3;
    int m = wid & 1, ng = wid >> 1;
    int px0 = ng * 32;
    float acc[4][4];
#pragma unroll
    for (int a = 0; a < 4; a++)
#pragma unroll
        for (int q = 0; q < 4; q++) acc[a][q] = 0.f;

#pragma unroll
    for (int s = 0; s < 8; s++) {
        const unsigned* ap = wAu + (m * 16 + gid) * 68 + s * 8 + ctid;
        unsigned a0 = ap[0], a1 = ap[8 * 68], a2 = ap[4], a3 = ap[8 * 68 + 4];
#pragma unroll
        for (int nt = 0; nt < 4; nt++) {
            int pxn = px0 + nt * 8 + gid;
            unsigned b0 = xsu[(s * 8 + ctid) * 136 + pxn];
            unsigned b1v = xsu[(s * 8 + ctid + 4) * 136 + pxn];
            mma16(acc[nt], a0, a1, a2, a3, b0, b1v);
        }
    }
    float* tb = g_t + b * C1 * HW + pin;
    int o0 = m * 16 + gid;
#pragma unroll
    for (int nt = 0; nt < 4; nt++) {
        int px = px0 + nt * 8 + 2 * ctid;
        float b0v = bs[o0], b1v = bs[o0 + 8];
        *(float2*)(tb + o0 * HW + px) =
            make_float2(fmaxf(acc[nt][0] + b0v, 0.f), fmaxf(acc[nt][1] + b0v, 0.f));
        *(float2*)(tb + (o0 + 8) * HW + px) =
            make_float2(fmaxf(acc[nt][2] + b1v, 0.f), fmaxf(acc[nt][3] + b1v, 0.f));
    }
}

// =====================================================================
// K23: fused conv2 + involution — 256 threads (R10 structure) with the
// x-halo interior loaded via cp.async at kernel start (overlaps staging
// + MMA without widening any barrier). Invalid halo cells zeroed by a
// disjoint predicated STS pass. Drain point: after the MMA sync.
// smem: wgt 49*520 f | tsu 16*520 u | wAu 64*20 u | bsm 64 f | xs 16128 f
// =====================================================================
#define XS_ROW 72
#define XS_CH  (14 * 72)
#define WGT_S  520
__global__ __launch_bounds__(256) void k23_conv2_inv(
    const float* __restrict__ x, const float* __restrict__ w2,
    const float* __restrict__ b2) {
    extern __shared__ float smf[];
    float* wgt = smf;                          // 49*520
    unsigned* tsu = (unsigned*)(smf + 49 * WGT_S);   // 16*520
    unsigned* wAu = tsu + 16 * WGT_S;          // 64*20
    float* bsm = (float*)(wAu + 64 * 20);      // 64
    float* xs  = bsm + 64;                     // 16*14*72
    int tid = threadIdx.x;
    int h0 = blockIdx.x * 8;
    int g  = blockIdx.y;
    int b  = blockIdx.z;

    // ---- (1) zero ONLY invalid halo cells (disjoint from cp.async dst) ----
    for (int idx = tid; idx < GC * 14 * XS_ROW; idx += 256) {
        int rem = idx % (14 * XS_ROW);
        int rr = rem / XS_ROW;
        int cc = rem - rr * XS_ROW;
        int hh = h0 - 3 + rr;
        int ws = cc - 3;
        if (!(hh >= 0 && hh < HH && ws >= 0 && ws < WW))
            xs[idx] = 0.f;
    }

    // ---- (2) cp.async interior (4B ops; dst col offset +3 forces 4B) ----
    {
        const float* xg = x + (b * DIM + g * GC) * HW;
        unsigned xsb = (unsigned)__cvta_generic_to_shared(xs);
        for (int idx = tid; idx < GC * 14 * 64; idx += 256) {
            int gc = idx / (14 * 64);
            int rem = idx - gc * (14 * 64);
            int rr = rem >> 6, ws = rem & 63;
            int hh = h0 - 3 + rr;
            if (hh >= 0 && hh < HH) {
                unsigned dst = xsb + (gc * XS_CH + rr * XS_ROW + ws + 3) * 4;
                const float* src = xg + gc * HW + hh * WW + ws;
                asm volatile("cp.async.ca.shared.global [%0], [%1], 4;\n"
                             :: "r"(dst), "l"(src));
            }
        }
        asm volatile("cp.async.commit_group;\n");
    }

    // ---- (3) stage t-tile, conv2 weights, bias ----
    const float* tb = g_t + b * C1 * HW + h0 * 64;
    for (int i = tid; i < 16 * 512; i += 256) {
        int c2 = i >> 9, px = i & 511;
        tsu[c2 * WGT_S + px] = packbf(tb[(2 * c2) * HW + px], tb[(2 * c2 + 1) * HW + px]);
    }
    for (int i = tid; i < 64 * 16; i += 256) {
        int o = i >> 4, c2 = i & 15;
        float a0 = 0.f, a1 = 0.f;
        if (o < 49) {
            int go = g * 49 + o;
            a0 = w2[go * C1 + 2 * c2];
            a1 = w2[go * C1 + 2 * c2 + 1];
        }
        wAu[o * 20 + c2] = packbf(a0, a1);
    }
    if (tid < 64) bsm[tid] = (tid < 49) ? b2[g * 49 + tid] : 0.f;
    __syncthreads();   // tsu/wAu/bsm ready (does NOT wait on cp.async)

    // ---- Phase A MMA: M=64(49), N=512, K=32; 8 warps = 4m × 2n ----
    int wid = tid >> 5, lane = tid & 31, gid = lane >> 2, ctid = lane & 3;
    int m = wid & 3, ng = wid >> 2;
    int orow = m * 16 + gid;
    float bb0 = bsm[orow], bb1 = bsm[orow + 8];
#pragma unroll
    for (int nh = 0; nh < 2; nh++) {
        float acc[16][4];
#pragma unroll
        for (int nt = 0; nt < 16; nt++)
#pragma unroll
            for (int q = 0; q < 4; q++) acc[nt][q] = 0.f;
#pragma unroll
        for (int s = 0; s < 2; s++) {
            const unsigned* ap = wAu + orow * 20 + s * 8 + ctid;
            unsigned a0 = ap[0], a1 = ap[8 * 20], a2 = ap[4], a3 = ap[8 * 20 + 4];
#pragma unroll
            for (int nt = 0; nt < 16; nt++) {
                int pxn = nh * 256 + ng * 128 + nt * 8 + gid;
                unsigned b0 = tsu[(s * 8 + ctid) * WGT_S + pxn];
                unsigned b1v = tsu[(s * 8 + ctid + 4) * WGT_S + pxn];
                mma16(acc[nt], a0, a1, a2, a3, b0, b1v);
            }
        }
#pragma unroll
        for (int nt = 0; nt < 16; nt++) {
            int px = nh * 256 + ng * 128 + nt * 8 + 2 * ctid;
            if (orow < 49)
                *(float2*)(wgt + orow * WGT_S + px) =
                    make_float2(acc[nt][0] + bb0, acc[nt][1] + bb0);
            if (orow + 8 < 49)
                *(float2*)(wgt + (orow + 8) * WGT_S + px) =
                    make_float2(acc[nt][2] + bb1, acc[nt][3] + bb1);
        }
    }
    __syncthreads();   // wgt visible

    // ---- drain x-halo cp.async, then barrier for cross-thread visibility ----
    asm volatile("cp.async.wait_group 0;\n");
    __syncthreads();

    // ---- stencil: thread = (gc-half, 4 px) ----
    int gcH = tid & 1;
    int pxq = tid >> 1;
    int r = pxq >> 4, w0 = (pxq & 15) * 4;
    float acc[8][4];
#pragma unroll
    for (int gc8 = 0; gc8 < 8; gc8++)
#pragma unroll
        for (int l = 0; l < 4; l++) acc[gc8][l] = 0.f;

    const float* wp = wgt + r * 64 + w0;
#pragma unroll
    for (int i = 0; i < KK; i++) {
        float4 wv[KK];
#pragma unroll
        for (int j = 0; j < KK; j++)
            wv[j] = *(const float4*)(wp + (i * KK + j) * WGT_S);
#pragma unroll
        for (int gc8 = 0; gc8 < 8; gc8++) {
            int gc = gcH * 8 + gc8;
            const float* xrow = xs + gc * XS_CH + (r + i) * XS_ROW + w0;
            float4 xa = *(const float4*)(xrow);
            float4 xb4 = *(const float4*)(xrow + 4);
            float4 xc = *(const float4*)(xrow + 8);
            float xw[12] = {xa.x, xa.y, xa.z, xa.w, xb4.x, xb4.y, xb4.z, xb4.w,
                            xc.x, xc.y, xc.z, xc.w};
#pragma unroll
            for (int j = 0; j < KK; j++) {
                acc[gc8][0] += wv[j].x * xw[j];
                acc[gc8][1] += wv[j].y * xw[j + 1];
                acc[gc8][2] += wv[j].z * xw[j + 2];
                acc[gc8][3] += wv[j].w * xw[j + 3];
            }
        }
    }
#pragma unroll
    for (int l = 0; l < 4; l++) {
        float* yo = g_y + (b * HW + (h0 + r) * WW + w0 + l) * DIM + g * GC + gcH * 8;
        *(float4*)(yo)     = make_float4(acc[0][l], acc[1][l], acc[2][l], acc[3][l]);
        *(float4*)(yo + 4) = make_float4(acc[4][l], acc[5][l], acc[6][l], acc[7][l]);
    }
}

// =====================================================================
// K4A: fused LN + pw1 + fast GELU — ldmatrix mainloop.
// M=128 f/block (of 256), N=128 px, K=128. grid (256,2), 256 thr, 2 CTAs/SM.
// =====================================================================
#define OT_S 130
__global__ __launch_bounds__(256, 2) void k4a_pw1(
    const float* __restrict__ p1w, const float* __restrict__ p1b,
    const float* __restrict__ lng_g, const float* __restrict__ lnb_g) {
    extern __shared__ unsigned smu[];
    unsigned* aT = smu;                        // 128*68 (weights, rows=f)
    unsigned* bT = smu + 128 * RS;             // 128*68 (LN(y), rows=px)
    float* b1s = (float*)(smu + 2 * 128 * RS); // 128
    float* lng = b1s + 128;                    // 128
    float* lnb = lng + 128;                    // 128
    float* outT = (float*)smu;                 // 128*130 (union)
    int tid = threadIdx.x;
    int f0 = blockIdx.y * 128;
    int pb = blockIdx.x * 128;

#pragma unroll
    for (int k = 0; k < 32; k++) {
        int i = tid + k * 256;
        int f = i >> 6, c2 = i & 63;
        float2 wv = *(const float2*)(p1w + (f0 + f) * 128 + 2 * c2);
        aT[f * RS + c2] = packbf(wv.x, wv.y);
    }
    if (tid < 128) {
        b1s[tid] = p1b[f0 + tid];
        lng[tid] = lng_g[tid];
        lnb[tid] = lnb_g[tid];
    }
    __syncthreads();   // lng/lnb visible

    // ---- fused LayerNorm: 2 threads / pixel, pack into bT ----
    {
        int p = tid >> 1, half = tid & 1;
        const float* yp = g_y + (pb + p) * DIM + half * 64;
        float4 v[16];
        float s = 0.f, q = 0.f;
#pragma unroll
        for (int i = 0; i < 16; i++) {
            v[i] = *(const float4*)(yp + i * 4);
            s += v[i].x + v[i].y + v[i].z + v[i].w;
            q += v[i].x*v[i].x + v[i].y*v[i].y + v[i].z*v[i].z + v[i].w*v[i].w;
        }
        s += __shfl_xor_sync(0xffffffffu, s, 1);
        q += __shfl_xor_sync(0xffffffffu, q, 1);
        float mu = s * (1.f / 128.f);
        float var = q * (1.f / 128.f) - mu * mu;
        float rs = rsqrtf(var + 1e-6f);
        unsigned* brow = bT + p * RS + half * 32;
#pragma unroll
        for (int i = 0; i < 16; i++) {
            int c = half * 64 + i * 4;
            float n0 = (v[i].x - mu) * rs * lng[c+0] + lnb[c+0];
            float n1 = (v[i].y - mu) * rs * lng[c+1] + lnb[c+1];
            float n2 = (v[i].z - mu) * rs * lng[c+2] + lnb[c+2];
            float n3 = (v[i].w - mu) * rs * lng[c+3] + lnb[c+3];
            brow[2 * i]     = packbf(n0, n1);
            brow[2 * i + 1] = packbf(n2, n3);
        }
    }
    __syncthreads();

    int wid = tid >> 5, lane = tid & 31;
    int m = wid & 3, ng = wid >> 2;
    unsigned aBase = (unsigned)__cvta_generic_to_shared(aT)
                   + (m * 32 + (lane & 15)) * RSB + (lane & 16);
    unsigned bBase = (unsigned)__cvta_generic_to_shared(bT)
                   + (ng * 64 + (lane & 7) + ((lane & 16) >> 1)) * RSB
                   + ((lane & 8) << 1);
    float acc[2][8][4];
#pragma unroll
    for (int mt = 0; mt < 2; mt++)
#pragma unroll
        for (int nt = 0; nt < 8; nt++)
#pragma unroll
            for (int q = 0; q < 4; q++) acc[mt][nt][q] = 0.f;

#pragma unroll
    for (int s = 0; s < 8; s++) {
        unsigned a[2][4];
#pragma unroll
        for (int mt = 0; mt < 2; mt++)
            ldsm4(a[mt][0], a[mt][1], a[mt][2], a[mt][3],
                  aBase + mt * 16 * RSB + s * 32);
#pragma unroll
        for (int ntp = 0; ntp < 4; ntp++) {
            unsigned b0, b1v, b2, b3;
            ldsm4(b0, b1v, b2, b3, bBase + ntp * 16 * RSB + s * 32);
#pragma unroll
            for (int mt = 0; mt < 2; mt++) {
                mma16(acc[mt][2 * ntp],     a[mt][0], a[mt][1], a[mt][2], a[mt][3], b0, b1v);
                mma16(acc[mt][2 * ntp + 1], a[mt][0], a[mt][1], a[mt][2], a[mt][3], b2, b3);
            }
        }
    }
    __syncthreads();   // operand buffers dead → outT

    int gid = lane >> 2, ctid = lane & 3;
#pragma unroll
    for (int mt = 0; mt < 2; mt++) {
        int frow = m * 32 + mt * 16 + gid;
        float bb0 = b1s[frow], bb1 = b1s[frow + 8];
#pragma unroll
        for (int nt = 0; nt < 8; nt++) {
            int px = ng * 64 + nt * 8 + 2 * ctid;
            *(float2*)(outT + frow * OT_S + px) =
                make_float2(gelu_fast(acc[mt][nt][0] + bb0), gelu_fast(acc[mt][nt][1] + bb0));
            *(float2*)(outT + (frow + 8) * OT_S + px) =
                make_float2(gelu_fast(acc[mt][nt][2] + bb1), gelu_fast(acc[mt][nt][3] + bb1));
        }
    }
    __syncthreads();

    // coalesced pack + store to g_hb [px][f/2]
    int fcol = f0 >> 1;
#pragma unroll
    for (int k = 0; k < 32; k++) {
        int i = tid + k * 256;
        int pxl = i >> 6, f2l = i & 63;
        float lo = outT[(2 * f2l) * OT_S + pxl];
        float hi = outT[(2 * f2l + 1) * OT_S + pxl];
        g_hb[(pb + pxl) * 128 + fcol + f2l] = packbf(lo, hi);
    }
}

// =====================================================================
// K4B: pw2 + bias + residual — ldmatrix mainloop. M=128 c, N=128 px,
// K=256 in 2 chunks. grid 256, block 256, 2 CTAs/SM.
// =====================================================================
__global__ __launch_bounds__(256, 2) void k4b_pw2(
    const float* __restrict__ p2w, const float* __restrict__ p2b,
    const float* __restrict__ x,   float* __restrict__ out) {
    extern __shared__ unsigned smu[];
    unsigned* aT = smu;                        // 128*68 (w2, rows=c)
    unsigned* bT = smu + 128 * RS;             // 128*68 (h, rows=px)
    float* b2s = (float*)(smu + 2 * 128 * RS); // 128
    float* outT = (float*)smu;                 // 128*130 (union)
    int tid = threadIdx.x;
    int pb = blockIdx.x * 128, b = pb >> 12, pin = pb & 4095;
    if (tid < 128) b2s[tid] = p2b[tid];

    int wid = tid >> 5, lane = tid & 31;
    int m = wid & 3, ng = wid >> 2;
    unsigned aBase = (unsigned)__cvta_generic_to_shared(aT)
                   + (m * 32 + (lane & 15)) * RSB + (lane & 16);
    unsigned bBase = (unsigned)__cvta_generic_to_shared(bT)
                   + (ng * 64 + (lane & 7) + ((lane & 16) >> 1)) * RSB
                   + ((lane & 8) << 1);
    float acc[2][8][4];
#pragma unroll
    for (int mt = 0; mt < 2; mt++)
#pragma unroll
        for (int nt = 0; nt < 8; nt++)
#pragma unroll
            for (int q = 0; q < 4; q++) acc[mt][nt][q] = 0.f;

    for (int kc = 0; kc < 2; kc++) {
        __syncthreads();
#pragma unroll
        for (int k = 0; k < 32; k++) {
            int i = tid + k * 256;
            int c = i >> 6, f2 = i & 63;
            float2 wv = *(const float2*)(p2w + c * 256 + kc * 128 + 2 * f2);
            aT[c * RS + f2] = packbf(wv.x, wv.y);
        }
#pragma unroll
        for (int k = 0; k < 32; k++) {
            int i = tid + k * 256;
            int p = i >> 6, f2 = i & 63;
            bT[p * RS + f2] = g_hb[(pb + p) * 128 + kc * 64 + f2];
        }
        __syncthreads();
#pragma unroll
        for (int s = 0; s < 8; s++) {
            unsigned a[2][4];
#pragma unroll
            for (int mt = 0; mt < 2; mt++)
                ldsm4(a[mt][0], a[mt][1], a[mt][2], a[mt][3],
                      aBase + mt * 16 * RSB + s * 32);
#pragma unroll
            for (int ntp = 0; ntp < 4; ntp++) {
                unsigned b0, b1v, b2v, b3;
                ldsm4(b0, b1v, b2v, b3, bBase + ntp * 16 * RSB + s * 32);
#pragma unroll
                for (int mt = 0; mt < 2; mt++) {
                    mma16(acc[mt][2 * ntp],     a[mt][0], a[mt][1], a[mt][2], a[mt][3], b0, b1v);
                    mma16(acc[mt][2 * ntp + 1], a[mt][0], a[mt][1], a[mt][2], a[mt][3], b2v, b3);
                }
            }
        }
    }
    __syncthreads();   // operand buffers dead → outT

    int gid = lane >> 2, ctid = lane & 3;
#pragma unroll
    for (int mt = 0; mt < 2; mt++) {
        int crow = m * 32 + mt * 16 + gid;
        float bb0 = b2s[crow], bb1 = b2s[crow + 8];
#pragma unroll
        for (int nt = 0; nt < 8; nt++) {
            int px = ng * 64 + nt * 8 + 2 * ctid;
            *(float2*)(outT + crow * OT_S + px) =
                make_float2(acc[mt][nt][0] + bb0, acc[mt][nt][1] + bb0);
            *(float2*)(outT + (crow + 8) * OT_S + px) =
                make_float2(acc[mt][nt][2] + bb1, acc[mt][nt][3] + bb1);
        }
    }
    __syncthreads();

    // coalesced residual + store (NCHW): 128 c × 64 px-pairs = 8192 float2
#pragma unroll
    for (int k = 0; k < 32; k++) {
        int i = tid + k * 256;
        int c = i >> 6, p2 = (i & 63) * 2;
        float2 v = *(const float2*)(outT + c * OT_S + p2);
        int base = (b * DIM + c) * HW + pin + p2;
        float2 xi = *(const float2*)(x + base);
        *(float2*)(out + base) = make_float2(v.x + xi.x, v.y + xi.y);
    }
}

// =====================================================================
extern "C" void kernel_launch(void* const* d_in, const int* in_sizes, int n_in,
                              void* d_out, int out_size) {
    const float* x    = (const float*)d_in[0];
    const float* c1w  = (const float*)d_in[1];
    const float* c1b  = (const float*)d_in[2];
    const float* bng  = (const float*)d_in[3];
    const float* bnb  = (const float*)d_in[4];
    const float* bnm  = (const float*)d_in[5];
    const float* bnv  = (const float*)d_in[6];
    const float* c2w  = (const float*)d_in[7];
    const float* c2b  = (const float*)d_in[8];
    const float* lng  = (const float*)d_in[9];
    const float* lnb  = (const float*)d_in[10];
    const float* p1w  = (const float*)d_in[11];
    const float* p1b  = (const float*)d_in[12];
    const float* p2w  = (const float*)d_in[13];
    const float* p2b  = (const float*)d_in[14];
    float* out = (float*)d_out;

    const int SM_K1  = (32 * 68 + 64 * 136 + 64) * 4;
    const int SM_K23 = (49 * WGT_S + 16 * WGT_S + 64 * 20 + 64 + GC * XS_CH) * 4;  // 205088
    const int SM_K4A = (2 * 128 * RS + 384) * 4;          // 71168 B
    const int SM_K4B = (2 * 128 * RS + 128) * 4;          // 70144 B

    cudaFuncSetAttribute(k1_conv1,      cudaFuncAttributeMaxDynamicSharedMemorySize, SM_K1);
    cudaFuncSetAttribute(k23_conv2_inv, cudaFuncAttributeMaxDynamicSharedMemorySize, SM_K23);
    cudaFuncSetAttribute(k4a_pw1,       cudaFuncAttributeMaxDynamicSharedMemorySize, SM_K4A);
    cudaFuncSetAttribute(k4b_pw2,       cudaFuncAttributeMaxDynamicSharedMemorySize, SM_K4B);

    k1_conv1<<<256, 256, SM_K1>>>(x, c1w, c1b, bng, bnb, bnm, bnv);
    k23_conv2_inv<<<dim3(8, 8, 8), 256, SM_K23>>>(x, c2w, c2b);
    k4a_pw1<<<dim3(256, 2), 256, SM_K4A>>>(p1w, p1b, lng, lnb);
    k4b_pw2<<<256, 256, SM_K4B>>>(p2w, p2b, x, out);
}

// round 14
// speedup vs baseline: 1.1521x; 1.0238x over previous
#include <cuda_runtime.h>
#include <cuda_bf16.h>
#include <math.h>

// Problem constants
#define BB   8
#define DIM  128
#define HH   64
#define WW   64
#define HW   4096
#define KK   7
#define GG   8
#define GC   16
#define C1   32
#define C2   392
#define NPIX 32768

// -------- scratch (device globals) --------
__device__ float g_t[BB * C1 * HW];           // conv1+bn+relu, NCHW fp32 (4 MB)
__device__ float g_y[NPIX * DIM];             // involution out, NHWC fp32 (17 MB)

// -------- helpers --------
__device__ __forceinline__ unsigned packbf(float lo, float hi) {
    unsigned r; asm("cvt.rn.bf16x2.f32 %0, %1, %2;" : "=r"(r) : "f"(hi), "f"(lo)); return r;
}
__device__ __forceinline__ void mma16(float* c, unsigned a0, unsigned a1,
                                      unsigned a2, unsigned a3,
                                      unsigned b0, unsigned b1) {
    asm volatile(
        "mma.sync.aligned.m16n8k16.row.col.f32.bf16.bf16.f32 "
        "{%0,%1,%2,%3}, {%4,%5,%6,%7}, {%8,%9}, {%0,%1,%2,%3};\n"
        : "+f"(c[0]), "+f"(c[1]), "+f"(c[2]), "+f"(c[3])
        : "r"(a0), "r"(a1), "r"(a2), "r"(a3), "r"(b0), "r"(b1));
}
__device__ __forceinline__ void ldsm4(unsigned& r0, unsigned& r1,
                                      unsigned& r2, unsigned& r3, unsigned addr) {
    asm volatile("ldmatrix.sync.aligned.m8n8.x4.shared.b16 {%0,%1,%2,%3}, [%4];\n"
        : "=r"(r0), "=r"(r1), "=r"(r2), "=r"(r3) : "r"(addr));
}
// tanh-form GELU (validated: rel_err unchanged at 1.79e-4)
__device__ __forceinline__ float gelu_fast(float z) {
    float u = z * (0.7978845608f + 0.0356774081f * z * z);
    float e = __expf(-2.f * u);
    return __fdividef(z, 1.f + e);
}

// ldmatrix operand row strides (u32 / bytes). Row start bank shift = 4.
#define RS   68
#define RSB  272
#define RS2  132
#define RSB2 528

// =====================================================================
// K1: t = relu(bn(conv1(x)))  — bf16 MMA, M=32, N=128px, K=128
// =====================================================================
__global__ __launch_bounds__(256) void k1_conv1(
    const float* __restrict__ x,  const float* __restrict__ w1,
    const float* __restrict__ b1, const float* __restrict__ bng,
    const float* __restrict__ bnb, const float* __restrict__ bnm,
    const float* __restrict__ bnv) {
    extern __shared__ unsigned smu[];
    unsigned* wAu = smu;                 // 32*68
    unsigned* xsu = smu + 32 * 68;       // 64*136
    float* bs = (float*)(xsu + 64 * 136);
    float* ss = bs + 32;
    int tid = threadIdx.x;

    if (tid < 32) {
        float sc = bng[tid] * rsqrtf(bnv[tid] + 1e-5f);
        ss[tid] = sc;
        bs[tid] = b1[tid] * sc + bnb[tid] - bnm[tid] * sc;
    }
    __syncthreads();
    for (int i = tid; i < 32 * 64; i += 256) {
        int o = i >> 6, c2 = i & 63;
        float sc = ss[o];
        wAu[o * 68 + c2] = packbf(w1[o * 128 + 2 * c2] * sc, w1[o * 128 + 2 * c2 + 1] * sc);
    }
    int pb = blockIdx.x * 128, b = pb >> 12, pin = pb & 4095;
    const float* xb = x + b * DIM * HW + pin;
    for (int i = tid; i < 64 * 128; i += 256) {
        int c2 = i >> 7, p = i & 127;
        xsu[c2 * 136 + p] = packbf(xb[(2 * c2) * HW + p], xb[(2 * c2 + 1) * HW + p]);
    }
    __syncthreads();

    int wid = tid >> 5, lane = tid & 31, gid = lane >> 2, ctid = lane & 3;
    int m = wid & 1, ng = wid >> 1;
    int px0 = ng * 32;
    float acc[4][4];
#pragma unroll
    for (int a = 0; a < 4; a++)
#pragma unroll
        for (int q = 0; q < 4; q++) acc[a][q] = 0.f;

#pragma unroll
    for (int s = 0; s < 8; s++) {
        const unsigned* ap = wAu + (m * 16 + gid) * 68 + s * 8 + ctid;
        unsigned a0 = ap[0], a1 = ap[8 * 68], a2 = ap[4], a3 = ap[8 * 68 + 4];
#pragma unroll
        for (int nt = 0; nt < 4; nt++) {
            int pxn = px0 + nt * 8 + gid;
            unsigned b0 = xsu[(s * 8 + ctid) * 136 + pxn];
            unsigned b1v = xsu[(s * 8 + ctid + 4) * 136 + pxn];
            mma16(acc[nt], a0, a1, a2, a3, b0, b1v);
        }
    }
    float* tb = g_t + b * C1 * HW + pin;
    int o0 = m * 16 + gid;
#pragma unroll
    for (int nt = 0; nt < 4; nt++) {
        int px = px0 + nt * 8 + 2 * ctid;
        float b0v = bs[o0], b1v = bs[o0 + 8];
        *(float2*)(tb + o0 * HW + px) =
            make_float2(fmaxf(acc[nt][0] + b0v, 0.f), fmaxf(acc[nt][1] + b0v, 0.f));
        *(float2*)(tb + (o0 + 8) * HW + px) =
            make_float2(fmaxf(acc[nt][2] + b1v, 0.f), fmaxf(acc[nt][3] + b1v, 0.f));
    }
}

// =====================================================================
// K23: fused conv2 + involution (exact R10 shape — best measured)
// =====================================================================
#define XS_ROW 72
#define XS_CH  (14 * 72)
#define WGT_S  520
__global__ __launch_bounds__(256) void k23_conv2_inv(
    const float* __restrict__ x, const float* __restrict__ w2,
    const float* __restrict__ b2) {
    extern __shared__ float smf[];
    float* wgt = smf;
    float* xs  = smf + 49 * WGT_S;
    unsigned* tsu = (unsigned*)xs;
    unsigned* wAu = tsu + 16 * WGT_S;
    float* bsm = (float*)(wAu + 64 * 20);
    int tid = threadIdx.x;
    int h0 = blockIdx.x * 8;
    int g  = blockIdx.y;
    int b  = blockIdx.z;

    const float* tb = g_t + b * C1 * HW + h0 * 64;
    for (int i = tid; i < 16 * 512; i += 256) {
        int c2 = i >> 9, px = i & 511;
        tsu[c2 * WGT_S + px] = packbf(tb[(2 * c2) * HW + px], tb[(2 * c2 + 1) * HW + px]);
    }
    for (int i = tid; i < 64 * 16; i += 256) {
        int o = i >> 4, c2 = i & 15;
        float a0 = 0.f, a1 = 0.f;
        if (o < 49) {
            int go = g * 49 + o;
            a0 = w2[go * C1 + 2 * c2];
            a1 = w2[go * C1 + 2 * c2 + 1];
        }
        wAu[o * 20 + c2] = packbf(a0, a1);
    }
    if (tid < 64) bsm[tid] = (tid < 49) ? b2[g * 49 + tid] : 0.f;
    __syncthreads();

    int wid = tid >> 5, lane = tid & 31, gid = lane >> 2, ctid = lane & 3;
    int m = wid & 3, ng = wid >> 2;
    int orow = m * 16 + gid;
    float bb0 = bsm[orow], bb1 = bsm[orow + 8];
#pragma unroll
    for (int nh = 0; nh < 2; nh++) {
        float acc[16][4];
#pragma unroll
        for (int nt = 0; nt < 16; nt++)
#pragma unroll
            for (int q = 0; q < 4; q++) acc[nt][q] = 0.f;
#pragma unroll
        for (int s = 0; s < 2; s++) {
            const unsigned* ap = wAu + orow * 20 + s * 8 + ctid;
            unsigned a0 = ap[0], a1 = ap[8 * 20], a2 = ap[4], a3 = ap[8 * 20 + 4];
#pragma unroll
            for (int nt = 0; nt < 16; nt++) {
                int pxn = nh * 256 + ng * 128 + nt * 8 + gid;
                unsigned b0 = tsu[(s * 8 + ctid) * WGT_S + pxn];
                unsigned b1v = tsu[(s * 8 + ctid + 4) * WGT_S + pxn];
                mma16(acc[nt], a0, a1, a2, a3, b0, b1v);
            }
        }
#pragma unroll
        for (int nt = 0; nt < 16; nt++) {
            int px = nh * 256 + ng * 128 + nt * 8 + 2 * ctid;
            if (orow < 49)
                *(float2*)(wgt + orow * WGT_S + px) =
                    make_float2(acc[nt][0] + bb0, acc[nt][1] + bb0);
            if (orow + 8 < 49)
                *(float2*)(wgt + (orow + 8) * WGT_S + px) =
                    make_float2(acc[nt][2] + bb1, acc[nt][3] + bb1);
        }
    }
    __syncthreads();

    for (int i = tid; i < GC * XS_CH; i += 256) xs[i] = 0.f;
    __syncthreads();
    const float* xg = x + (b * DIM + g * GC) * HW;
    for (int idx = tid; idx < GC * 14 * 64; idx += 256) {
        int gc = idx / (14 * 64);
        int rem = idx - gc * (14 * 64);
        int rr = rem >> 6, ww = rem & 63;
        int hh = h0 - 3 + rr;
        if (hh >= 0 && hh < HH)
            xs[gc * XS_CH + rr * XS_ROW + ww + 3] = xg[gc * HW + hh * WW + ww];
    }
    __syncthreads();

    int gcH = tid & 1;
    int pxq = tid >> 1;
    int r = pxq >> 4, w0 = (pxq & 15) * 4;
    float acc[8][4];
#pragma unroll
    for (int gc8 = 0; gc8 < 8; gc8++)
#pragma unroll
        for (int l = 0; l < 4; l++) acc[gc8][l] = 0.f;

    const float* wp = wgt + r * 64 + w0;
#pragma unroll
    for (int i = 0; i < KK; i++) {
        float4 wv[KK];
#pragma unroll
        for (int j = 0; j < KK; j++)
            wv[j] = *(const float4*)(wp + (i * KK + j) * WGT_S);
#pragma unroll
        for (int gc8 = 0; gc8 < 8; gc8++) {
            int gc = gcH * 8 + gc8;
            const float* xrow = xs + gc * XS_CH + (r + i) * XS_ROW + w0;
            float4 xa = *(const float4*)(xrow);
            float4 xb4 = *(const float4*)(xrow + 4);
            float4 xc = *(const float4*)(xrow + 8);
            float xw[12] = {xa.x, xa.y, xa.z, xa.w, xb4.x, xb4.y, xb4.z, xb4.w,
                            xc.x, xc.y, xc.z, xc.w};
#pragma unroll
            for (int j = 0; j < KK; j++) {
                acc[gc8][0] += wv[j].x * xw[j];
                acc[gc8][1] += wv[j].y * xw[j + 1];
                acc[gc8][2] += wv[j].z * xw[j + 2];
                acc[gc8][3] += wv[j].w * xw[j + 3];
            }
        }
    }
#pragma unroll
    for (int l = 0; l < 4; l++) {
        float* yo = g_y + (b * HW + (h0 + r) * WW + w0 + l) * DIM + g * GC + gcH * 8;
        *(float4*)(yo)     = make_float4(acc[0][l], acc[1][l], acc[2][l], acc[3][l]);
        *(float4*)(yo + 4) = make_float4(acc[4][l], acc[5][l], acc[6][l], acc[7][l]);
    }
}

// =====================================================================
// K4: fully fused LN + pw1 + GELU + pw2 + residual, per 128-px tile.
// grid 256, 256 thr, 1 CTA/SM.
// smem (u32): Aw[8704] | bT[8704] | hB[128*132] | w2T[128*132] | params[640]
//  - Aw holds one 128-f half of w1 (reloaded for half 1); also unions the
//    64x130 f32 transpose scratch for pw1 epilogues.
//  - hB holds GELU(h) as bf16 f-pairs in ldmatrix row layout [px][f2].
//  - w2T region also unions the 128x130 f32 pw2 epilogue scratch.
// =====================================================================
#define OFF_A 0
#define OFF_B 8704
#define OFF_C 17408
#define OFF_D 34304
#define OFF_P 51200
#define SMU_TOT 51840
__global__ __launch_bounds__(256, 1) void k4_fused(
    const float* __restrict__ p1w, const float* __restrict__ p1b,
    const float* __restrict__ lng_g, const float* __restrict__ lnb_g,
    const float* __restrict__ p2w, const float* __restrict__ p2b,
    const float* __restrict__ x,   float* __restrict__ out) {
    extern __shared__ unsigned smu[];
    unsigned* Aw  = smu + OFF_A;               // 128*68
    unsigned* bT  = smu + OFF_B;               // 128*68
    unsigned* hB  = smu + OFF_C;               // 128*132
    unsigned* w2T = smu + OFF_D;               // 128*132
    float* b1s = (float*)(smu + OFF_P);        // 256
    float* b2s = b1s + 256;                    // 128
    float* lng = b2s + 128;                    // 128
    float* lnb = lng + 128;                    // 128
    float* outT  = (float*)(smu + OFF_A);      // 64*130 scratch (union Aw)
    float* outT2 = (float*)(smu + OFF_D);      // 128*130 scratch (union w2T)
    int tid = threadIdx.x;
    int pb = blockIdx.x * 128, b = pb >> 12, pin = pb & 4095;

    // ---- phase 1a: stage w1 half0, w2T, params ----
#pragma unroll
    for (int k = 0; k < 32; k++) {
        int i = tid + k * 256;
        int f = i >> 6, c2 = i & 63;
        float2 wv = *(const float2*)(p1w + f * 128 + 2 * c2);
        Aw[f * RS + c2] = packbf(wv.x, wv.y);
    }
#pragma unroll 8
    for (int k = 0; k < 64; k++) {
        int i = tid + k * 256;
        int c = i >> 7, f2 = i & 127;
        float2 wv = *(const float2*)(p2w + c * 256 + 2 * f2);
        w2T[c * RS2 + f2] = packbf(wv.x, wv.y);
    }
    b1s[tid] = p1b[tid];
    if (tid < 128) {
        b2s[tid] = p2b[tid];
        lng[tid] = lng_g[tid];
        lnb[tid] = lnb_g[tid];
    }
    __syncthreads();   // lng/lnb visible for LN

    // ---- phase 1b: LN (2 thr/px) → bT ----
    {
        int p = tid >> 1, half = tid & 1;
        const float* yp = g_y + (pb + p) * DIM + half * 64;
        float4 v[16];
        float s = 0.f, q = 0.f;
#pragma unroll
        for (int i = 0; i < 16; i++) {
            v[i] = *(const float4*)(yp + i * 4);
            s += v[i].x + v[i].y + v[i].z + v[i].w;
            q += v[i].x*v[i].x + v[i].y*v[i].y + v[i].z*v[i].z + v[i].w*v[i].w;
        }
        s += __shfl_xor_sync(0xffffffffu, s, 1);
        q += __shfl_xor_sync(0xffffffffu, q, 1);
        float mu = s * (1.f / 128.f);
        float var = q * (1.f / 128.f) - mu * mu;
        float rs = rsqrtf(var + 1e-6f);
        unsigned* brow = bT + p * RS + half * 32;
#pragma unroll
        for (int i = 0; i < 16; i++) {
            int c = half * 64 + i * 4;
            float n0 = (v[i].x - mu) * rs * lng[c+0] + lnb[c+0];
            float n1 = (v[i].y - mu) * rs * lng[c+1] + lnb[c+1];
            float n2 = (v[i].z - mu) * rs * lng[c+2] + lnb[c+2];
            float n3 = (v[i].w - mu) * rs * lng[c+3] + lnb[c+3];
            brow[2 * i]     = packbf(n0, n1);
            brow[2 * i + 1] = packbf(n2, n3);
        }
    }
    __syncthreads();

    int wid = tid >> 5, lane = tid & 31, gid = lane >> 2, ctid = lane & 3;
    int m = wid & 3, ng = wid >> 2;
    unsigned aBase1 = (unsigned)__cvta_generic_to_shared(Aw)
                    + (m * 32 + (lane & 15)) * RSB + (lane & 16);
    unsigned bBase1 = (unsigned)__cvta_generic_to_shared(bT)
                    + (ng * 64 + (lane & 7) + ((lane & 16) >> 1)) * RSB
                    + ((lane & 8) << 1);

    // ---- pw1: two f-halves of 128 ----
    for (int hf = 0; hf < 2; hf++) {
        if (hf == 1) {
            __syncthreads();   // outT(Aw) scratch fully consumed
#pragma unroll
            for (int k = 0; k < 32; k++) {
                int i = tid + k * 256;
                int f = i >> 6, c2 = i & 63;
                float2 wv = *(const float2*)(p1w + (128 + f) * 128 + 2 * c2);
                Aw[f * RS + c2] = packbf(wv.x, wv.y);
            }
            __syncthreads();
        }
        float acc[2][8][4];
#pragma unroll
        for (int mt = 0; mt < 2; mt++)
#pragma unroll
            for (int nt = 0; nt < 8; nt++)
#pragma unroll
                for (int q = 0; q < 4; q++) acc[mt][nt][q] = 0.f;
#pragma unroll
        for (int s = 0; s < 8; s++) {
            unsigned a[2][4];
#pragma unroll
            for (int mt = 0; mt < 2; mt++)
                ldsm4(a[mt][0], a[mt][1], a[mt][2], a[mt][3],
                      aBase1 + mt * 16 * RSB + s * 32);
#pragma unroll
            for (int ntp = 0; ntp < 4; ntp++) {
                unsigned b0, b1v, b2v, b3;
                ldsm4(b0, b1v, b2v, b3, bBase1 + ntp * 16 * RSB + s * 32);
#pragma unroll
                for (int mt = 0; mt < 2; mt++) {
                    mma16(acc[mt][2 * ntp],     a[mt][0], a[mt][1], a[mt][2], a[mt][3], b0, b1v);
                    mma16(acc[mt][2 * ntp + 1], a[mt][0], a[mt][1], a[mt][2], a[mt][3], b2v, b3);
                }
            }
        }
        // ---- epilogue in two 64-f parts through outT(Aw union) ----
#pragma unroll
        for (int pt = 0; pt < 2; pt++) {
            __syncthreads();   // Aw/outT free (MMA reads done / prev repack done)
            if ((m >> 1) == pt) {
                int lm = m & 1;
#pragma unroll
                for (int mt = 0; mt < 2; mt++) {
                    int lrow = lm * 32 + mt * 16 + gid;              // 0..63
                    int frow = hf * 128 + pt * 64 + lrow;            // global f
                    float bb0 = b1s[frow], bb1 = b1s[frow + 8];
#pragma unroll
                    for (int nt = 0; nt < 8; nt++) {
                        int px = ng * 64 + nt * 8 + 2 * ctid;
                        *(float2*)(outT + lrow * 130 + px) =
                            make_float2(gelu_fast(acc[mt][nt][0] + bb0),
                                        gelu_fast(acc[mt][nt][1] + bb0));
                        *(float2*)(outT + (lrow + 8) * 130 + px) =
                            make_float2(gelu_fast(acc[mt][nt][2] + bb1),
                                        gelu_fast(acc[mt][nt][3] + bb1));
                    }
                }
            }
            __syncthreads();
            // repack outT[64f][128px] → hB[px][f2] (4096 pairs)
            int colbase = hf * 64 + pt * 32;
#pragma unroll
            for (int k = 0; k < 16; k++) {
                int i = tid + k * 256;
                int f2l = i >> 7, pxl = i & 127;
                float lo = outT[(2 * f2l) * 130 + pxl];
                float hi = outT[(2 * f2l + 1) * 130 + pxl];
                hB[pxl * RS2 + colbase + f2l] = packbf(lo, hi);
            }
        }
    }
    __syncthreads();   // hB complete

    // ---- pw2: M=128 c, K=256 (16 s-steps over hB/w2T) ----
    unsigned aBase2 = (unsigned)__cvta_generic_to_shared(w2T)
                    + (m * 32 + (lane & 15)) * RSB2 + (lane & 16);
    unsigned bBase2 = (unsigned)__cvta_generic_to_shared(hB)
                    + (ng * 64 + (lane & 7) + ((lane & 16) >> 1)) * RSB2
                    + ((lane & 8) << 1);
    float acc2[2][8][4];
#pragma unroll
    for (int mt = 0; mt < 2; mt++)
#pragma unroll
        for (int nt = 0; nt < 8; nt++)
#pragma unroll
            for (int q = 0; q < 4; q++) acc2[mt][nt][q] = 0.f;
#pragma unroll
    for (int s = 0; s < 16; s++) {
        unsigned a[2][4];
#pragma unroll
        for (int mt = 0; mt < 2; mt++)
            ldsm4(a[mt][0], a[mt][1], a[mt][2], a[mt][3],
                  aBase2 + mt * 16 * RSB2 + s * 32);
#pragma unroll
        for (int ntp = 0; ntp < 4; ntp++) {
            unsigned b0, b1v, b2v, b3;
            ldsm4(b0, b1v, b2v, b3, bBase2 + ntp * 16 * RSB2 + s * 32);
#pragma unroll
            for (int mt = 0; mt < 2; mt++) {
                mma16(acc2[mt][2 * ntp],     a[mt][0], a[mt][1], a[mt][2], a[mt][3], b0, b1v);
                mma16(acc2[mt][2 * ntp + 1], a[mt][0], a[mt][1], a[mt][2], a[mt][3], b2v, b3);
            }
        }
    }
    __syncthreads();   // w2T dead → outT2

#pragma unroll
    for (int mt = 0; mt < 2; mt++) {
        int crow = m * 32 + mt * 16 + gid;
        float bb0 = b2s[crow], bb1 = b2s[crow + 8];
#pragma unroll
        for (int nt = 0; nt < 8; nt++) {
            int px = ng * 64 + nt * 8 + 2 * ctid;
            *(float2*)(outT2 + crow * 130 + px) =
                make_float2(acc2[mt][nt][0] + bb0, acc2[mt][nt][1] + bb0);
            *(float2*)(outT2 + (crow + 8) * 130 + px) =
                make_float2(acc2[mt][nt][2] + bb1, acc2[mt][nt][3] + bb1);
        }
    }
    __syncthreads();

    // coalesced residual + store (NCHW): 128 c × 64 px-pairs = 8192 float2
#pragma unroll
    for (int k = 0; k < 32; k++) {
        int i = tid + k * 256;
        int c = i >> 6, p2 = (i & 63) * 2;
        float2 v = *(const float2*)(outT2 + c * 130 + p2);
        int base = (b * DIM + c) * HW + pin + p2;
        float2 xi = *(const float2*)(x + base);
        *(float2*)(out + base) = make_float2(v.x + xi.x, v.y + xi.y);
    }
}

// =====================================================================
extern "C" void kernel_launch(void* const* d_in, const int* in_sizes, int n_in,
                              void* d_out, int out_size) {
    const float* x    = (const float*)d_in[0];
    const float* c1w  = (const float*)d_in[1];
    const float* c1b  = (const float*)d_in[2];
    const float* bng  = (const float*)d_in[3];
    const float* bnb  = (const float*)d_in[4];
    const float* bnm  = (const float*)d_in[5];
    const float* bnv  = (const float*)d_in[6];
    const float* c2w  = (const float*)d_in[7];
    const float* c2b  = (const float*)d_in[8];
    const float* lng  = (const float*)d_in[9];
    const float* lnb  = (const float*)d_in[10];
    const float* p1w  = (const float*)d_in[11];
    const float* p1b  = (const float*)d_in[12];
    const float* p2w  = (const float*)d_in[13];
    const float* p2b  = (const float*)d_in[14];
    float* out = (float*)d_out;

    const int SM_K1  = (32 * 68 + 64 * 136 + 64) * 4;
    const int SM_K23 = (49 * WGT_S + GC * XS_CH) * 4;     // 166432 (R10 shape)
    const int SM_K4  = SMU_TOT * 4;                       // 207360

    cudaFuncSetAttribute(k1_conv1,      cudaFuncAttributeMaxDynamicSharedMemorySize, SM_K1);
    cudaFuncSetAttribute(k23_conv2_inv, cudaFuncAttributeMaxDynamicSharedMemorySize, SM_K23);
    cudaFuncSetAttribute(k4_fused,      cudaFuncAttributeMaxDynamicSharedMemorySize, SM_K4);

    k1_conv1<<<256, 256, SM_K1>>>(x, c1w, c1b, bng, bnb, bnm, bnv);
    k23_conv2_inv<<<dim3(8, 8, 8), 256, SM_K23>>>(x, c2w, c2b);
    k4_fused<<<256, 256, SM_K4>>>(p1w, p1b, lng, lnb, p2w, p2b, x, out);
}

// round 15
// speedup vs baseline: 1.2216x; 1.0603x over previous
#include <cuda_runtime.h>
#include <cuda_bf16.h>
#include <math.h>

// Problem constants
#define BB   8
#define DIM  128
#define HH   64
#define WW   64
#define HW   4096
#define KK   7
#define GG   8
#define GC   16
#define C1   32
#define C2   392
#define NPIX 32768

// -------- scratch (device globals) --------
__device__ float g_t[BB * C1 * HW];           // conv1+bn+relu, NCHW fp32 (4 MB)
__device__ float g_y[NPIX * DIM];             // involution out, NHWC fp32 (17 MB)

// -------- helpers --------
__device__ __forceinline__ unsigned packbf(float lo, float hi) {
    unsigned r; asm("cvt.rn.bf16x2.f32 %0, %1, %2;" : "=r"(r) : "f"(hi), "f"(lo)); return r;
}
__device__ __forceinline__ void mma16(float* c, unsigned a0, unsigned a1,
                                      unsigned a2, unsigned a3,
                                      unsigned b0, unsigned b1) {
    asm volatile(
        "mma.sync.aligned.m16n8k16.row.col.f32.bf16.bf16.f32 "
        "{%0,%1,%2,%3}, {%4,%5,%6,%7}, {%8,%9}, {%0,%1,%2,%3};\n"
        : "+f"(c[0]), "+f"(c[1]), "+f"(c[2]), "+f"(c[3])
        : "r"(a0), "r"(a1), "r"(a2), "r"(a3), "r"(b0), "r"(b1));
}
__device__ __forceinline__ void ldsm4(unsigned& r0, unsigned& r1,
                                      unsigned& r2, unsigned& r3, unsigned addr) {
    asm volatile("ldmatrix.sync.aligned.m8n8.x4.shared.b16 {%0,%1,%2,%3}, [%4];\n"
        : "=r"(r0), "=r"(r1), "=r"(r2), "=r"(r3) : "r"(addr));
}
// tanh-form GELU (validated: rel_err unchanged at 1.79e-4)
__device__ __forceinline__ float gelu_fast(float z) {
    float u = z * (0.7978845608f + 0.0356774081f * z * z);
    float e = __expf(-2.f * u);
    return __fdividef(z, 1.f + e);
}

// ldmatrix operand row strides (u32 / bytes)
#define RS   68
#define RSB  272
#define RS2  132
#define RSB2 528

// =====================================================================
// K1: t = relu(bn(conv1(x)))  — bf16 MMA, M=32, N=64px, K=128.
// grid 512 (2x parallelism vs R14; latency-bound kernel).
// =====================================================================
__global__ __launch_bounds__(256) void k1_conv1(
    const float* __restrict__ x,  const float* __restrict__ w1,
    const float* __restrict__ b1, const float* __restrict__ bng,
    const float* __restrict__ bnb, const float* __restrict__ bnm,
    const float* __restrict__ bnv) {
    extern __shared__ unsigned smu[];
    unsigned* wAu = smu;                 // 32*68
    unsigned* xsu = smu + 32 * 68;       // 64*72
    float* bs = (float*)(xsu + 64 * 72);
    float* ss = bs + 32;
    int tid = threadIdx.x;

    if (tid < 32) {
        float sc = bng[tid] * rsqrtf(bnv[tid] + 1e-5f);
        ss[tid] = sc;
        bs[tid] = b1[tid] * sc + bnb[tid] - bnm[tid] * sc;
    }
    __syncthreads();
    for (int i = tid; i < 32 * 64; i += 256) {
        int o = i >> 6, c2 = i & 63;
        float sc = ss[o];
        wAu[o * 68 + c2] = packbf(w1[o * 128 + 2 * c2] * sc, w1[o * 128 + 2 * c2 + 1] * sc);
    }
    int pb = blockIdx.x * 64, b = pb >> 12, pin = pb & 4095;
    const float* xb = x + b * DIM * HW + pin;
    for (int i = tid; i < 64 * 64; i += 256) {
        int c2 = i >> 6, p = i & 63;
        xsu[c2 * 72 + p] = packbf(xb[(2 * c2) * HW + p], xb[(2 * c2 + 1) * HW + p]);
    }
    __syncthreads();

    int wid = tid >> 5, lane = tid & 31, gid = lane >> 2, ctid = lane & 3;
    int m = wid & 1, ng = wid >> 1;
    int px0 = ng * 16;
    float acc[2][4];
#pragma unroll
    for (int a = 0; a < 2; a++)
#pragma unroll
        for (int q = 0; q < 4; q++) acc[a][q] = 0.f;

#pragma unroll
    for (int s = 0; s < 8; s++) {
        const unsigned* ap = wAu + (m * 16 + gid) * 68 + s * 8 + ctid;
        unsigned a0 = ap[0], a1 = ap[8 * 68], a2 = ap[4], a3 = ap[8 * 68 + 4];
#pragma unroll
        for (int nt = 0; nt < 2; nt++) {
            int pxn = px0 + nt * 8 + gid;
            unsigned b0 = xsu[(s * 8 + ctid) * 72 + pxn];
            unsigned b1v = xsu[(s * 8 + ctid + 4) * 72 + pxn];
            mma16(acc[nt], a0, a1, a2, a3, b0, b1v);
        }
    }
    float* tb = g_t + b * C1 * HW + pin;
    int o0 = m * 16 + gid;
#pragma unroll
    for (int nt = 0; nt < 2; nt++) {
        int px = px0 + nt * 8 + 2 * ctid;
        float b0v = bs[o0], b1v = bs[o0 + 8];
        *(float2*)(tb + o0 * HW + px) =
            make_float2(fmaxf(acc[nt][0] + b0v, 0.f), fmaxf(acc[nt][1] + b0v, 0.f));
        *(float2*)(tb + (o0 + 8) * HW + px) =
            make_float2(fmaxf(acc[nt][2] + b1v, 0.f), fmaxf(acc[nt][3] + b1v, 0.f));
    }
}

// =====================================================================
// K23: fused conv2 + involution (exact R10 shape — best measured)
// =====================================================================
#define XS_ROW 72
#define XS_CH  (14 * 72)
#define WGT_S  520
__global__ __launch_bounds__(256) void k23_conv2_inv(
    const float* __restrict__ x, const float* __restrict__ w2,
    const float* __restrict__ b2) {
    extern __shared__ float smf[];
    float* wgt = smf;
    float* xs  = smf + 49 * WGT_S;
    unsigned* tsu = (unsigned*)xs;
    unsigned* wAu = tsu + 16 * WGT_S;
    float* bsm = (float*)(wAu + 64 * 20);
    int tid = threadIdx.x;
    int h0 = blockIdx.x * 8;
    int g  = blockIdx.y;
    int b  = blockIdx.z;

    const float* tb = g_t + b * C1 * HW + h0 * 64;
    for (int i = tid; i < 16 * 512; i += 256) {
        int c2 = i >> 9, px = i & 511;
        tsu[c2 * WGT_S + px] = packbf(tb[(2 * c2) * HW + px], tb[(2 * c2 + 1) * HW + px]);
    }
    for (int i = tid; i < 64 * 16; i += 256) {
        int o = i >> 4, c2 = i & 15;
        float a0 = 0.f, a1 = 0.f;
        if (o < 49) {
            int go = g * 49 + o;
            a0 = w2[go * C1 + 2 * c2];
            a1 = w2[go * C1 + 2 * c2 + 1];
        }
        wAu[o * 20 + c2] = packbf(a0, a1);
    }
    if (tid < 64) bsm[tid] = (tid < 49) ? b2[g * 49 + tid] : 0.f;
    __syncthreads();

    int wid = tid >> 5, lane = tid & 31, gid = lane >> 2, ctid = lane & 3;
    int m = wid & 3, ng = wid >> 2;
    int orow = m * 16 + gid;
    float bb0 = bsm[orow], bb1 = bsm[orow + 8];
#pragma unroll
    for (int nh = 0; nh < 2; nh++) {
        float acc[16][4];
#pragma unroll
        for (int nt = 0; nt < 16; nt++)
#pragma unroll
            for (int q = 0; q < 4; q++) acc[nt][q] = 0.f;
#pragma unroll
        for (int s = 0; s < 2; s++) {
            const unsigned* ap = wAu + orow * 20 + s * 8 + ctid;
            unsigned a0 = ap[0], a1 = ap[8 * 20], a2 = ap[4], a3 = ap[8 * 20 + 4];
#pragma unroll
            for (int nt = 0; nt < 16; nt++) {
                int pxn = nh * 256 + ng * 128 + nt * 8 + gid;
                unsigned b0 = tsu[(s * 8 + ctid) * WGT_S + pxn];
                unsigned b1v = tsu[(s * 8 + ctid + 4) * WGT_S + pxn];
                mma16(acc[nt], a0, a1, a2, a3, b0, b1v);
            }
        }
#pragma unroll
        for (int nt = 0; nt < 16; nt++) {
            int px = nh * 256 + ng * 128 + nt * 8 + 2 * ctid;
            if (orow < 49)
                *(float2*)(wgt + orow * WGT_S + px) =
                    make_float2(acc[nt][0] + bb0, acc[nt][1] + bb0);
            if (orow + 8 < 49)
                *(float2*)(wgt + (orow + 8) * WGT_S + px) =
                    make_float2(acc[nt][2] + bb1, acc[nt][3] + bb1);
        }
    }
    __syncthreads();

    for (int i = tid; i < GC * XS_CH; i += 256) xs[i] = 0.f;
    __syncthreads();
    const float* xg = x + (b * DIM + g * GC) * HW;
    for (int idx = tid; idx < GC * 14 * 64; idx += 256) {
        int gc = idx / (14 * 64);
        int rem = idx - gc * (14 * 64);
        int rr = rem >> 6, ww = rem & 63;
        int hh = h0 - 3 + rr;
        if (hh >= 0 && hh < HH)
            xs[gc * XS_CH + rr * XS_ROW + ww + 3] = xg[gc * HW + hh * WW + ww];
    }
    __syncthreads();

    int gcH = tid & 1;
    int pxq = tid >> 1;
    int r = pxq >> 4, w0 = (pxq & 15) * 4;
    float acc[8][4];
#pragma unroll
    for (int gc8 = 0; gc8 < 8; gc8++)
#pragma unroll
        for (int l = 0; l < 4; l++) acc[gc8][l] = 0.f;

    const float* wp = wgt + r * 64 + w0;
#pragma unroll
    for (int i = 0; i < KK; i++) {
        float4 wv[KK];
#pragma unroll
        for (int j = 0; j < KK; j++)
            wv[j] = *(const float4*)(wp + (i * KK + j) * WGT_S);
#pragma unroll
        for (int gc8 = 0; gc8 < 8; gc8++) {
            int gc = gcH * 8 + gc8;
            const float* xrow = xs + gc * XS_CH + (r + i) * XS_ROW + w0;
            float4 xa = *(const float4*)(xrow);
            float4 xb4 = *(const float4*)(xrow + 4);
            float4 xc = *(const float4*)(xrow + 8);
            float xw[12] = {xa.x, xa.y, xa.z, xa.w, xb4.x, xb4.y, xb4.z, xb4.w,
                            xc.x, xc.y, xc.z, xc.w};
#pragma unroll
            for (int j = 0; j < KK; j++) {
                acc[gc8][0] += wv[j].x * xw[j];
                acc[gc8][1] += wv[j].y * xw[j + 1];
                acc[gc8][2] += wv[j].z * xw[j + 2];
                acc[gc8][3] += wv[j].w * xw[j + 3];
            }
        }
    }
#pragma unroll
    for (int l = 0; l < 4; l++) {
        float* yo = g_y + (b * HW + (h0 + r) * WW + w0 + l) * DIM + g * GC + gcH * 8;
        *(float4*)(yo)     = make_float4(acc[0][l], acc[1][l], acc[2][l], acc[3][l]);
        *(float4*)(yo + 4) = make_float4(acc[4][l], acc[5][l], acc[6][l], acc[7][l]);
    }
}

// =====================================================================
// K4: fused LN + pw1 + GELU + pw2 + residual — permuted-K direct path.
// pw1 epilogue writes GELU bf16 pairs (f, f+8) straight into hB[px][kp]
// with kp = (f>>4)*8 + (f&7); w2T packs the same pairs. No transpose
// scratch, no warp-idle phases. 8 syncs.
// grid 256, 256 thr, 1 CTA/SM.
// =====================================================================
#define OFF_A 0
#define OFF_B 8704
#define OFF_C 17408
#define OFF_D 34304
#define OFF_P 51200
#define SMU_TOT 51840
__global__ __launch_bounds__(256, 1) void k4_fused(
    const float* __restrict__ p1w, const float* __restrict__ p1b,
    const float* __restrict__ lng_g, const float* __restrict__ lnb_g,
    const float* __restrict__ p2w, const float* __restrict__ p2b,
    const float* __restrict__ x,   float* __restrict__ out) {
    extern __shared__ unsigned smu[];
    unsigned* Aw  = smu + OFF_A;               // 128*68
    unsigned* bT  = smu + OFF_B;               // 128*68
    unsigned* hB  = smu + OFF_C;               // 128*132
    unsigned* w2T = smu + OFF_D;               // 128*132
    float* b1s = (float*)(smu + OFF_P);        // 256
    float* b2s = b1s + 256;                    // 128
    float* lng = b2s + 128;                    // 128
    float* lnb = lng + 128;                    // 128
    float* outT2 = (float*)(smu + OFF_D);      // 128*130 scratch (union w2T)
    int tid = threadIdx.x;
    int pb = blockIdx.x * 128, b = pb >> 12, pin = pb & 4095;

    // ---- stage w1 half0, w2T (permuted-K pairs), params ----
#pragma unroll
    for (int k = 0; k < 32; k++) {
        int i = tid + k * 256;
        int f = i >> 6, c2 = i & 63;
        float2 wv = *(const float2*)(p1w + f * 128 + 2 * c2);
        Aw[f * RS + c2] = packbf(wv.x, wv.y);
    }
#pragma unroll 8
    for (int k = 0; k < 64; k++) {
        int i = tid + k * 256;
        int c = i >> 7, kp = i & 127;
        int hf = kp >> 6, loc = kp & 63;
        int f = hf * 128 + ((loc >> 3) << 4) + (loc & 7);
        float lo = p2w[c * 256 + f];
        float hi = p2w[c * 256 + f + 8];
        w2T[c * RS2 + kp] = packbf(lo, hi);
    }
    b1s[tid] = p1b[tid];
    if (tid < 128) {
        b2s[tid] = p2b[tid];
        lng[tid] = lng_g[tid];
        lnb[tid] = lnb_g[tid];
    }
    __syncthreads();

    // ---- LN (2 thr/px) → bT ----
    {
        int p = tid >> 1, half = tid & 1;
        const float* yp = g_y + (pb + p) * DIM + half * 64;
        float4 v[16];
        float s = 0.f, q = 0.f;
#pragma unroll
        for (int i = 0; i < 16; i++) {
            v[i] = *(const float4*)(yp + i * 4);
            s += v[i].x + v[i].y + v[i].z + v[i].w;
            q += v[i].x*v[i].x + v[i].y*v[i].y + v[i].z*v[i].z + v[i].w*v[i].w;
        }
        s += __shfl_xor_sync(0xffffffffu, s, 1);
        q += __shfl_xor_sync(0xffffffffu, q, 1);
        float mu = s * (1.f / 128.f);
        float var = q * (1.f / 128.f) - mu * mu;
        float rs = rsqrtf(var + 1e-6f);
        unsigned* brow = bT + p * RS + half * 32;
#pragma unroll
        for (int i = 0; i < 16; i++) {
            int c = half * 64 + i * 4;
            float n0 = (v[i].x - mu) * rs * lng[c+0] + lnb[c+0];
            float n1 = (v[i].y - mu) * rs * lng[c+1] + lnb[c+1];
            float n2 = (v[i].z - mu) * rs * lng[c+2] + lnb[c+2];
            float n3 = (v[i].w - mu) * rs * lng[c+3] + lnb[c+3];
            brow[2 * i]     = packbf(n0, n1);
            brow[2 * i + 1] = packbf(n2, n3);
        }
    }
    __syncthreads();

    int wid = tid >> 5, lane = tid & 31, gid = lane >> 2, ctid = lane & 3;
    int m = wid & 3, ng = wid >> 2;
    unsigned aBase1 = (unsigned)__cvta_generic_to_shared(Aw)
                    + (m * 32 + (lane & 15)) * RSB + (lane & 16);
    unsigned bBase1 = (unsigned)__cvta_generic_to_shared(bT)
                    + (ng * 64 + (lane & 7) + ((lane & 16) >> 1)) * RSB
                    + ((lane & 8) << 1);

    // ---- pw1: two f-halves; direct STS to hB (permuted-K) ----
    for (int hf = 0; hf < 2; hf++) {
        if (hf == 1) {
            __syncthreads();   // all warps done reading Aw (hf0 MMA complete)
#pragma unroll
            for (int k = 0; k < 32; k++) {
                int i = tid + k * 256;
                int f = i >> 6, c2 = i & 63;
                float2 wv = *(const float2*)(p1w + (128 + f) * 128 + 2 * c2);
                Aw[f * RS + c2] = packbf(wv.x, wv.y);
            }
            __syncthreads();
        }
        float acc[2][8][4];
#pragma unroll
        for (int mt = 0; mt < 2; mt++)
#pragma unroll
            for (int nt = 0; nt < 8; nt++)
#pragma unroll
                for (int q = 0; q < 4; q++) acc[mt][nt][q] = 0.f;
#pragma unroll
        for (int s = 0; s < 8; s++) {
            unsigned a[2][4];
#pragma unroll
            for (int mt = 0; mt < 2; mt++)
                ldsm4(a[mt][0], a[mt][1], a[mt][2], a[mt][3],
                      aBase1 + mt * 16 * RSB + s * 32);
#pragma unroll
            for (int ntp = 0; ntp < 4; ntp++) {
                unsigned b0, b1v, b2v, b3;
                ldsm4(b0, b1v, b2v, b3, bBase1 + ntp * 16 * RSB + s * 32);
#pragma unroll
                for (int mt = 0; mt < 2; mt++) {
                    mma16(acc[mt][2 * ntp],     a[mt][0], a[mt][1], a[mt][2], a[mt][3], b0, b1v);
                    mma16(acc[mt][2 * ntp + 1], a[mt][0], a[mt][1], a[mt][2], a[mt][3], b2v, b3);
                }
            }
        }
        // direct epilogue: GELU + pack (f, f+8) → hB[px][hf*64 + kp]
#pragma unroll
        for (int mt = 0; mt < 2; mt++) {
            int frow = m * 32 + mt * 16 + gid;               // f with (f&8)==0
            int kp = hf * 64 + ((frow >> 4) << 3) + (frow & 7);
            float bb0 = b1s[hf * 128 + frow];
            float bb1 = b1s[hf * 128 + frow + 8];
#pragma unroll
            for (int nt = 0; nt < 8; nt++) {
                int px = ng * 64 + nt * 8 + 2 * ctid;
                hB[px * RS2 + kp] =
                    packbf(gelu_fast(acc[mt][nt][0] + bb0),
                           gelu_fast(acc[mt][nt][2] + bb1));
                hB[(px + 1) * RS2 + kp] =
                    packbf(gelu_fast(acc[mt][nt][1] + bb0),
                           gelu_fast(acc[mt][nt][3] + bb1));
            }
        }
    }
    __syncthreads();   // hB complete

    // ---- pw2: M=128 c, K=256 (16 s-steps over permuted kp) ----
    unsigned aBase2 = (unsigned)__cvta_generic_to_shared(w2T)
                    + (m * 32 + (lane & 15)) * RSB2 + (lane & 16);
    unsigned bBase2 = (unsigned)__cvta_generic_to_shared(hB)
                    + (ng * 64 + (lane & 7) + ((lane & 16) >> 1)) * RSB2
                    + ((lane & 8) << 1);
    float acc2[2][8][4];
#pragma unroll
    for (int mt = 0; mt < 2; mt++)
#pragma unroll
        for (int nt = 0; nt < 8; nt++)
#pragma unroll
            for (int q = 0; q < 4; q++) acc2[mt][nt][q] = 0.f;
#pragma unroll
    for (int s = 0; s < 16; s++) {
        unsigned a[2][4];
#pragma unroll
        for (int mt = 0; mt < 2; mt++)
            ldsm4(a[mt][0], a[mt][1], a[mt][2], a[mt][3],
                  aBase2 + mt * 16 * RSB2 + s * 32);
#pragma unroll
        for (int ntp = 0; ntp < 4; ntp++) {
            unsigned b0, b1v, b2v, b3;
            ldsm4(b0, b1v, b2v, b3, bBase2 + ntp * 16 * RSB2 + s * 32);
#pragma unroll
            for (int mt = 0; mt < 2; mt++) {
                mma16(acc2[mt][2 * ntp],     a[mt][0], a[mt][1], a[mt][2], a[mt][3], b0, b1v);
                mma16(acc2[mt][2 * ntp + 1], a[mt][0], a[mt][1], a[mt][2], a[mt][3], b2v, b3);
            }
        }
    }
    __syncthreads();   // w2T dead → outT2

#pragma unroll
    for (int mt = 0; mt < 2; mt++) {
        int crow = m * 32 + mt * 16 + gid;
        float bb0 = b2s[crow], bb1 = b2s[crow + 8];
#pragma unroll
        for (int nt = 0; nt < 8; nt++) {
            int px = ng * 64 + nt * 8 + 2 * ctid;
            *(float2*)(outT2 + crow * 130 + px) =
                make_float2(acc2[mt][nt][0] + bb0, acc2[mt][nt][1] + bb0);
            *(float2*)(outT2 + (crow + 8) * 130 + px) =
                make_float2(acc2[mt][nt][2] + bb1, acc2[mt][nt][3] + bb1);
        }
    }
    __syncthreads();

    // coalesced residual + store (NCHW): 128 c × 64 px-pairs = 8192 float2
#pragma unroll
    for (int k = 0; k < 32; k++) {
        int i = tid + k * 256;
        int c = i >> 6, p2 = (i & 63) * 2;
        float2 v = *(const float2*)(outT2 + c * 130 + p2);
        int base = (b * DIM + c) * HW + pin + p2;
        float2 xi = *(const float2*)(x + base);
        *(float2*)(out + base) = make_float2(v.x + xi.x, v.y + xi.y);
    }
}

// =====================================================================
extern "C" void kernel_launch(void* const* d_in, const int* in_sizes, int n_in,
                              void* d_out, int out_size) {
    const float* x    = (const float*)d_in[0];
    const float* c1w  = (const float*)d_in[1];
    const float* c1b  = (const float*)d_in[2];
    const float* bng  = (const float*)d_in[3];
    const float* bnb  = (const float*)d_in[4];
    const float* bnm  = (const float*)d_in[5];
    const float* bnv  = (const float*)d_in[6];
    const float* c2w  = (const float*)d_in[7];
    const float* c2b  = (const float*)d_in[8];
    const float* lng  = (const float*)d_in[9];
    const float* lnb  = (const float*)d_in[10];
    const float* p1w  = (const float*)d_in[11];
    const float* p1b  = (const float*)d_in[12];
    const float* p2w  = (const float*)d_in[13];
    const float* p2b  = (const float*)d_in[14];
    float* out = (float*)d_out;

    const int SM_K1  = (32 * 68 + 64 * 72 + 64) * 4;      // 27392
    const int SM_K23 = (49 * WGT_S + GC * XS_CH) * 4;     // 166432
    const int SM_K4  = SMU_TOT * 4;                       // 207360

    cudaFuncSetAttribute(k1_conv1,      cudaFuncAttributeMaxDynamicSharedMemorySize, SM_K1);
    cudaFuncSetAttribute(k23_conv2_inv, cudaFuncAttributeMaxDynamicSharedMemorySize, SM_K23);
    cudaFuncSetAttribute(k4_fused,      cudaFuncAttributeMaxDynamicSharedMemorySize, SM_K4);

    k1_conv1<<<512, 256, SM_K1>>>(x, c1w, c1b, bng, bnb, bnm, bnv);
    k23_conv2_inv<<<dim3(8, 8, 8), 256, SM_K23>>>(x, c2w, c2b);
    k4_fused<<<256, 256, SM_K4>>>(p1w, p1b, lng, lnb, p2w, p2b, x, out);
}

// round 16
// speedup vs baseline: 1.2546x; 1.0270x over previous
#include <cuda_runtime.h>
#include <cuda_bf16.h>
#include <math.h>

// Problem constants
#define BB   8
#define DIM  128
#define HH   64
#define WW   64
#define HW   4096
#define KK   7
#define GG   8
#define GC   16
#define C1   32
#define C2   392
#define NPIX 32768

// -------- scratch (device globals) --------
__device__ unsigned g_tb[BB * 16 * HW];       // conv1+bn+relu, bf16 c-pairs [b][c2][px] (2 MB)
__device__ float    g_y[NPIX * DIM];          // involution out, NHWC fp32 (17 MB)

// -------- helpers --------
__device__ __forceinline__ unsigned packbf(float lo, float hi) {
    unsigned r; asm("cvt.rn.bf16x2.f32 %0, %1, %2;" : "=r"(r) : "f"(hi), "f"(lo)); return r;
}
__device__ __forceinline__ void mma16(float* c, unsigned a0, unsigned a1,
                                      unsigned a2, unsigned a3,
                                      unsigned b0, unsigned b1) {
    asm volatile(
        "mma.sync.aligned.m16n8k16.row.col.f32.bf16.bf16.f32 "
        "{%0,%1,%2,%3}, {%4,%5,%6,%7}, {%8,%9}, {%0,%1,%2,%3};\n"
        : "+f"(c[0]), "+f"(c[1]), "+f"(c[2]), "+f"(c[3])
        : "r"(a0), "r"(a1), "r"(a2), "r"(a3), "r"(b0), "r"(b1));
}
__device__ __forceinline__ void ldsm4(unsigned& r0, unsigned& r1,
                                      unsigned& r2, unsigned& r3, unsigned addr) {
    asm volatile("ldmatrix.sync.aligned.m8n8.x4.shared.b16 {%0,%1,%2,%3}, [%4];\n"
        : "=r"(r0), "=r"(r1), "=r"(r2), "=r"(r3) : "r"(addr));
}
// tanh-form GELU (validated: rel_err unchanged at 1.79e-4)
__device__ __forceinline__ float gelu_fast(float z) {
    float u = z * (0.7978845608f + 0.0356774081f * z * z);
    float e = __expf(-2.f * u);
    return __fdividef(z, 1.f + e);
}

// ldmatrix operand row strides (u32 / bytes)
#define RS   68
#define RSB  272
#define RS2  132
#define RSB2 528

// =====================================================================
// K1: t = relu(bn(conv1(x)))  — bf16 MMA, M=32, N=128px, K=128.
// R14 geometry (grid 256; best measured). Epilogue packs bf16 c-pairs
// via smem and writes g_tb in k23's staging layout.
// =====================================================================
__global__ __launch_bounds__(256) void k1_conv1(
    const float* __restrict__ x,  const float* __restrict__ w1,
    const float* __restrict__ b1, const float* __restrict__ bng,
    const float* __restrict__ bnb, const float* __restrict__ bnm,
    const float* __restrict__ bnv) {
    extern __shared__ unsigned smu[];
    unsigned* wAu = smu;                 // 32*68
    unsigned* xsu = smu + 32 * 68;       // 64*136 (reused as ts f32 32*132)
    float* bs = (float*)(xsu + 64 * 136);
    float* ss = bs + 32;
    float* ts = (float*)xsu;             // epilogue scratch (union)
    int tid = threadIdx.x;

    if (tid < 32) {
        float sc = bng[tid] * rsqrtf(bnv[tid] + 1e-5f);
        ss[tid] = sc;
        bs[tid] = b1[tid] * sc + bnb[tid] - bnm[tid] * sc;
    }
    __syncthreads();
    for (int i = tid; i < 32 * 64; i += 256) {
        int o = i >> 6, c2 = i & 63;
        float sc = ss[o];
        wAu[o * 68 + c2] = packbf(w1[o * 128 + 2 * c2] * sc, w1[o * 128 + 2 * c2 + 1] * sc);
    }
    int pb = blockIdx.x * 128, b = pb >> 12, pin = pb & 4095;
    const float* xb = x + b * DIM * HW + pin;
    for (int i = tid; i < 64 * 128; i += 256) {
        int c2 = i >> 7, p = i & 127;
        xsu[c2 * 136 + p] = packbf(xb[(2 * c2) * HW + p], xb[(2 * c2 + 1) * HW + p]);
    }
    __syncthreads();

    int wid = tid >> 5, lane = tid & 31, gid = lane >> 2, ctid = lane & 3;
    int m = wid & 1, ng = wid >> 1;
    int px0 = ng * 32;
    float acc[4][4];
#pragma unroll
    for (int a = 0; a < 4; a++)
#pragma unroll
        for (int q = 0; q < 4; q++) acc[a][q] = 0.f;

#pragma unroll
    for (int s = 0; s < 8; s++) {
        const unsigned* ap = wAu + (m * 16 + gid) * 68 + s * 8 + ctid;
        unsigned a0 = ap[0], a1 = ap[8 * 68], a2 = ap[4], a3 = ap[8 * 68 + 4];
#pragma unroll
        for (int nt = 0; nt < 4; nt++) {
            int pxn = px0 + nt * 8 + gid;
            unsigned b0 = xsu[(s * 8 + ctid) * 136 + pxn];
            unsigned b1v = xsu[(s * 8 + ctid + 4) * 136 + pxn];
            mma16(acc[nt], a0, a1, a2, a3, b0, b1v);
        }
    }
    __syncthreads();   // xsu reads done → ts scratch

    int o0 = m * 16 + gid;
    float b0v = bs[o0], b1v = bs[o0 + 8];
#pragma unroll
    for (int nt = 0; nt < 4; nt++) {
        int px = px0 + nt * 8 + 2 * ctid;
        *(float2*)(ts + o0 * 132 + px) =
            make_float2(fmaxf(acc[nt][0] + b0v, 0.f), fmaxf(acc[nt][1] + b0v, 0.f));
        *(float2*)(ts + (o0 + 8) * 132 + px) =
            make_float2(fmaxf(acc[nt][2] + b1v, 0.f), fmaxf(acc[nt][3] + b1v, 0.f));
    }
    __syncthreads();

    // pack c-pairs → g_tb [b][c2][px] (coalesced u32 stores)
    unsigned* tbo = g_tb + b * 16 * HW + pin;
#pragma unroll
    for (int k = 0; k < 8; k++) {
        int i = tid + k * 256;
        int c2 = i >> 7, p = i & 127;
        tbo[c2 * HW + p] = packbf(ts[(2 * c2) * 132 + p], ts[(2 * c2 + 1) * 132 + p]);
    }
}

// =====================================================================
// K23: fused conv2 + involution (R10 compute shape; t staged as direct
// u32 copy from g_tb — no packbf, 16 MB less DRAM than fp32 path)
// =====================================================================
#define XS_ROW 72
#define XS_CH  (14 * 72)
#define WGT_S  520
__global__ __launch_bounds__(256) void k23_conv2_inv(
    const float* __restrict__ x, const float* __restrict__ w2,
    const float* __restrict__ b2) {
    extern __shared__ float smf[];
    float* wgt = smf;
    float* xs  = smf + 49 * WGT_S;
    unsigned* tsu = (unsigned*)xs;
    unsigned* wAu = tsu + 16 * WGT_S;
    float* bsm = (float*)(wAu + 64 * 20);
    int tid = threadIdx.x;
    int h0 = blockIdx.x * 8;
    int g  = blockIdx.y;
    int b  = blockIdx.z;

    const unsigned* tbp = g_tb + b * 16 * HW + h0 * 64;
    for (int i = tid; i < 16 * 512; i += 256) {
        int c2 = i >> 9, px = i & 511;
        tsu[c2 * WGT_S + px] = tbp[c2 * HW + px];
    }
    for (int i = tid; i < 64 * 16; i += 256) {
        int o = i >> 4, c2 = i & 15;
        float a0 = 0.f, a1 = 0.f;
        if (o < 49) {
            int go = g * 49 + o;
            a0 = w2[go * C1 + 2 * c2];
            a1 = w2[go * C1 + 2 * c2 + 1];
        }
        wAu[o * 20 + c2] = packbf(a0, a1);
    }
    if (tid < 64) bsm[tid] = (tid < 49) ? b2[g * 49 + tid] : 0.f;
    __syncthreads();

    int wid = tid >> 5, lane = tid & 31, gid = lane >> 2, ctid = lane & 3;
    int m = wid & 3, ng = wid >> 2;
    int orow = m * 16 + gid;
    float bb0 = bsm[orow], bb1 = bsm[orow + 8];
#pragma unroll
    for (int nh = 0; nh < 2; nh++) {
        float acc[16][4];
#pragma unroll
        for (int nt = 0; nt < 16; nt++)
#pragma unroll
            for (int q = 0; q < 4; q++) acc[nt][q] = 0.f;
#pragma unroll
        for (int s = 0; s < 2; s++) {
            const unsigned* ap = wAu + orow * 20 + s * 8 + ctid;
            unsigned a0 = ap[0], a1 = ap[8 * 20], a2 = ap[4], a3 = ap[8 * 20 + 4];
#pragma unroll
            for (int nt = 0; nt < 16; nt++) {
                int pxn = nh * 256 + ng * 128 + nt * 8 + gid;
                unsigned b0 = tsu[(s * 8 + ctid) * WGT_S + pxn];
                unsigned b1v = tsu[(s * 8 + ctid + 4) * WGT_S + pxn];
                mma16(acc[nt], a0, a1, a2, a3, b0, b1v);
            }
        }
#pragma unroll
        for (int nt = 0; nt < 16; nt++) {
            int px = nh * 256 + ng * 128 + nt * 8 + 2 * ctid;
            if (orow < 49)
                *(float2*)(wgt + orow * WGT_S + px) =
                    make_float2(acc[nt][0] + bb0, acc[nt][1] + bb0);
            if (orow + 8 < 49)
                *(float2*)(wgt + (orow + 8) * WGT_S + px) =
                    make_float2(acc[nt][2] + bb1, acc[nt][3] + bb1);
        }
    }
    __syncthreads();

    for (int i = tid; i < GC * XS_CH; i += 256) xs[i] = 0.f;
    __syncthreads();
    const float* xg = x + (b * DIM + g * GC) * HW;
    for (int idx = tid; idx < GC * 14 * 64; idx += 256) {
        int gc = idx / (14 * 64);
        int rem = idx - gc * (14 * 64);
        int rr = rem >> 6, ww = rem & 63;
        int hh = h0 - 3 + rr;
        if (hh >= 0 && hh < HH)
            xs[gc * XS_CH + rr * XS_ROW + ww + 3] = xg[gc * HW + hh * WW + ww];
    }
    __syncthreads();

    int gcH = tid & 1;
    int pxq = tid >> 1;
    int r = pxq >> 4, w0 = (pxq & 15) * 4;
    float acc[8][4];
#pragma unroll
    for (int gc8 = 0; gc8 < 8; gc8++)
#pragma unroll
        for (int l = 0; l < 4; l++) acc[gc8][l] = 0.f;

    const float* wp = wgt + r * 64 + w0;
#pragma unroll
    for (int i = 0; i < KK; i++) {
        float4 wv[KK];
#pragma unroll
        for (int j = 0; j < KK; j++)
            wv[j] = *(const float4*)(wp + (i * KK + j) * WGT_S);
#pragma unroll
        for (int gc8 = 0; gc8 < 8; gc8++) {
            int gc = gcH * 8 + gc8;
            const float* xrow = xs + gc * XS_CH + (r + i) * XS_ROW + w0;
            float4 xa = *(const float4*)(xrow);
            float4 xb4 = *(const float4*)(xrow + 4);
            float4 xc = *(const float4*)(xrow + 8);
            float xw[12] = {xa.x, xa.y, xa.z, xa.w, xb4.x, xb4.y, xb4.z, xb4.w,
                            xc.x, xc.y, xc.z, xc.w};
#pragma unroll
            for (int j = 0; j < KK; j++) {
                acc[gc8][0] += wv[j].x * xw[j];
                acc[gc8][1] += wv[j].y * xw[j + 1];
                acc[gc8][2] += wv[j].z * xw[j + 2];
                acc[gc8][3] += wv[j].w * xw[j + 3];
            }
        }
    }
#pragma unroll
    for (int l = 0; l < 4; l++) {
        float* yo = g_y + (b * HW + (h0 + r) * WW + w0 + l) * DIM + g * GC + gcH * 8;
        *(float4*)(yo)     = make_float4(acc[0][l], acc[1][l], acc[2][l], acc[3][l]);
        *(float4*)(yo + 4) = make_float4(acc[4][l], acc[5][l], acc[6][l], acc[7][l]);
    }
}

// =====================================================================
// K4: fused LN + pw1 + GELU + pw2 + residual — permuted-K direct path
// (unchanged from R15 best).
// =====================================================================
#define OFF_A 0
#define OFF_B 8704
#define OFF_C 17408
#define OFF_D 34304
#define OFF_P 51200
#define SMU_TOT 51840
__global__ __launch_bounds__(256, 1) void k4_fused(
    const float* __restrict__ p1w, const float* __restrict__ p1b,
    const float* __restrict__ lng_g, const float* __restrict__ lnb_g,
    const float* __restrict__ p2w, const float* __restrict__ p2b,
    const float* __restrict__ x,   float* __restrict__ out) {
    extern __shared__ unsigned smu[];
    unsigned* Aw  = smu + OFF_A;
    unsigned* bT  = smu + OFF_B;
    unsigned* hB  = smu + OFF_C;
    unsigned* w2T = smu + OFF_D;
    float* b1s = (float*)(smu + OFF_P);
    float* b2s = b1s + 256;
    float* lng = b2s + 128;
    float* lnb = lng + 128;
    float* outT2 = (float*)(smu + OFF_D);
    int tid = threadIdx.x;
    int pb = blockIdx.x * 128, b = pb >> 12, pin = pb & 4095;

#pragma unroll
    for (int k = 0; k < 32; k++) {
        int i = tid + k * 256;
        int f = i >> 6, c2 = i & 63;
        float2 wv = *(const float2*)(p1w + f * 128 + 2 * c2);
        Aw[f * RS + c2] = packbf(wv.x, wv.y);
    }
#pragma unroll 8
    for (int k = 0; k < 64; k++) {
        int i = tid + k * 256;
        int c = i >> 7, kp = i & 127;
        int hf = kp >> 6, loc = kp & 63;
        int f = hf * 128 + ((loc >> 3) << 4) + (loc & 7);
        float lo = p2w[c * 256 + f];
        float hi = p2w[c * 256 + f + 8];
        w2T[c * RS2 + kp] = packbf(lo, hi);
    }
    b1s[tid] = p1b[tid];
    if (tid < 128) {
        b2s[tid] = p2b[tid];
        lng[tid] = lng_g[tid];
        lnb[tid] = lnb_g[tid];
    }
    __syncthreads();

    {
        int p = tid >> 1, half = tid & 1;
        const float* yp = g_y + (pb + p) * DIM + half * 64;
        float4 v[16];
        float s = 0.f, q = 0.f;
#pragma unroll
        for (int i = 0; i < 16; i++) {
            v[i] = *(const float4*)(yp + i * 4);
            s += v[i].x + v[i].y + v[i].z + v[i].w;
            q += v[i].x*v[i].x + v[i].y*v[i].y + v[i].z*v[i].z + v[i].w*v[i].w;
        }
        s += __shfl_xor_sync(0xffffffffu, s, 1);
        q += __shfl_xor_sync(0xffffffffu, q, 1);
        float mu = s * (1.f / 128.f);
        float var = q * (1.f / 128.f) - mu * mu;
        float rs = rsqrtf(var + 1e-6f);
        unsigned* brow = bT + p * RS + half * 32;
#pragma unroll
        for (int i = 0; i < 16; i++) {
            int c = half * 64 + i * 4;
            float n0 = (v[i].x - mu) * rs * lng[c+0] + lnb[c+0];
            float n1 = (v[i].y - mu) * rs * lng[c+1] + lnb[c+1];
            float n2 = (v[i].z - mu) * rs * lng[c+2] + lnb[c+2];
            float n3 = (v[i].w - mu) * rs * lng[c+3] + lnb[c+3];
            brow[2 * i]     = packbf(n0, n1);
            brow[2 * i + 1] = packbf(n2, n3);
        }
    }
    __syncthreads();

    int wid = tid >> 5, lane = tid & 31, gid = lane >> 2, ctid = lane & 3;
    int m = wid & 3, ng = wid >> 2;
    unsigned aBase1 = (unsigned)__cvta_generic_to_shared(Aw)
                    + (m * 32 + (lane & 15)) * RSB + (lane & 16);
    unsigned bBase1 = (unsigned)__cvta_generic_to_shared(bT)
                    + (ng * 64 + (lane & 7) + ((lane & 16) >> 1)) * RSB
                    + ((lane & 8) << 1);

    for (int hf = 0; hf < 2; hf++) {
        if (hf == 1) {
            __syncthreads();
#pragma unroll
            for (int k = 0; k < 32; k++) {
                int i = tid + k * 256;
                int f = i >> 6, c2 = i & 63;
                float2 wv = *(const float2*)(p1w + (128 + f) * 128 + 2 * c2);
                Aw[f * RS + c2] = packbf(wv.x, wv.y);
            }
            __syncthreads();
        }
        float acc[2][8][4];
#pragma unroll
        for (int mt = 0; mt < 2; mt++)
#pragma unroll
            for (int nt = 0; nt < 8; nt++)
#pragma unroll
                for (int q = 0; q < 4; q++) acc[mt][nt][q] = 0.f;
#pragma unroll
        for (int s = 0; s < 8; s++) {
            unsigned a[2][4];
#pragma unroll
            for (int mt = 0; mt < 2; mt++)
                ldsm4(a[mt][0], a[mt][1], a[mt][2], a[mt][3],
                      aBase1 + mt * 16 * RSB + s * 32);
#pragma unroll
            for (int ntp = 0; ntp < 4; ntp++) {
                unsigned b0, b1v, b2v, b3;
                ldsm4(b0, b1v, b2v, b3, bBase1 + ntp * 16 * RSB + s * 32);
#pragma unroll
                for (int mt = 0; mt < 2; mt++) {
                    mma16(acc[mt][2 * ntp],     a[mt][0], a[mt][1], a[mt][2], a[mt][3], b0, b1v);
                    mma16(acc[mt][2 * ntp + 1], a[mt][0], a[mt][1], a[mt][2], a[mt][3], b2v, b3);
                }
            }
        }
#pragma unroll
        for (int mt = 0; mt < 2; mt++) {
            int frow = m * 32 + mt * 16 + gid;
            int kp = hf * 64 + ((frow >> 4) << 3) + (frow & 7);
            float bb0 = b1s[hf * 128 + frow];
            float bb1 = b1s[hf * 128 + frow + 8];
#pragma unroll
            for (int nt = 0; nt < 8; nt++) {
                int px = ng * 64 + nt * 8 + 2 * ctid;
                hB[px * RS2 + kp] =
                    packbf(gelu_fast(acc[mt][nt][0] + bb0),
                           gelu_fast(acc[mt][nt][2] + bb1));
                hB[(px + 1) * RS2 + kp] =
                    packbf(gelu_fast(acc[mt][nt][1] + bb0),
                           gelu_fast(acc[mt][nt][3] + bb1));
            }
        }
    }
    __syncthreads();

    unsigned aBase2 = (unsigned)__cvta_generic_to_shared(w2T)
                    + (m * 32 + (lane & 15)) * RSB2 + (lane & 16);
    unsigned bBase2 = (unsigned)__cvta_generic_to_shared(hB)
                    + (ng * 64 + (lane & 7) + ((lane & 16) >> 1)) * RSB2
                    + ((lane & 8) << 1);
    float acc2[2][8][4];
#pragma unroll
    for (int mt = 0; mt < 2; mt++)
#pragma unroll
        for (int nt = 0; nt < 8; nt++)
#pragma unroll
            for (int q = 0; q < 4; q++) acc2[mt][nt][q] = 0.f;
#pragma unroll
    for (int s = 0; s < 16; s++) {
        unsigned a[2][4];
#pragma unroll
        for (int mt = 0; mt < 2; mt++)
            ldsm4(a[mt][0], a[mt][1], a[mt][2], a[mt][3],
                  aBase2 + mt * 16 * RSB2 + s * 32);
#pragma unroll
        for (int ntp = 0; ntp < 4; ntp++) {
            unsigned b0, b1v, b2v, b3;
            ldsm4(b0, b1v, b2v, b3, bBase2 + ntp * 16 * RSB2 + s * 32);
#pragma unroll
            for (int mt = 0; mt < 2; mt++) {
                mma16(acc2[mt][2 * ntp],     a[mt][0], a[mt][1], a[mt][2], a[mt][3], b0, b1v);
                mma16(acc2[mt][2 * ntp + 1], a[mt][0], a[mt][1], a[mt][2], a[mt][3], b2v, b3);
            }
        }
    }
    __syncthreads();

#pragma unroll
    for (int mt = 0; mt < 2; mt++) {
        int crow = m * 32 + mt * 16 + gid;
        float bb0 = b2s[crow], bb1 = b2s[crow + 8];
#pragma unroll
        for (int nt = 0; nt < 8; nt++) {
            int px = ng * 64 + nt * 8 + 2 * ctid;
            *(float2*)(outT2 + crow * 130 + px) =
                make_float2(acc2[mt][nt][0] + bb0, acc2[mt][nt][1] + bb0);
            *(float2*)(outT2 + (crow + 8) * 130 + px) =
                make_float2(acc2[mt][nt][2] + bb1, acc2[mt][nt][3] + bb1);
        }
    }
    __syncthreads();

#pragma unroll
    for (int k = 0; k < 32; k++) {
        int i = tid + k * 256;
        int c = i >> 6, p2 = (i & 63) * 2;
        float2 v = *(const float2*)(outT2 + c * 130 + p2);
        int base = (b * DIM + c) * HW + pin + p2;
        float2 xi = *(const float2*)(x + base);
        *(float2*)(out + base) = make_float2(v.x + xi.x, v.y + xi.y);
    }
}

// =====================================================================
extern "C" void kernel_launch(void* const* d_in, const int* in_sizes, int n_in,
                              void* d_out, int out_size) {
    const float* x    = (const float*)d_in[0];
    const float* c1w  = (const float*)d_in[1];
    const float* c1b  = (const float*)d_in[2];
    const float* bng  = (const float*)d_in[3];
    const float* bnb  = (const float*)d_in[4];
    const float* bnm  = (const float*)d_in[5];
    const float* bnv  = (const float*)d_in[6];
    const float* c2w  = (const float*)d_in[7];
    const float* c2b  = (const float*)d_in[8];
    const float* lng  = (const float*)d_in[9];
    const float* lnb  = (const float*)d_in[10];
    const float* p1w  = (const float*)d_in[11];
    const float* p1b  = (const float*)d_in[12];
    const float* p2w  = (const float*)d_in[13];
    const float* p2b  = (const float*)d_in[14];
    float* out = (float*)d_out;

    const int SM_K1  = (32 * 68 + 64 * 136 + 64) * 4;
    const int SM_K23 = (49 * WGT_S + GC * XS_CH) * 4;
    const int SM_K4  = SMU_TOT * 4;

    cudaFuncSetAttribute(k1_conv1,      cudaFuncAttributeMaxDynamicSharedMemorySize, SM_K1);
    cudaFuncSetAttribute(k23_conv2_inv, cudaFuncAttributeMaxDynamicSharedMemorySize, SM_K23);
    cudaFuncSetAttribute(k4_fused,      cudaFuncAttributeMaxDynamicSharedMemorySize, SM_K4);

    k1_conv1<<<256, 256, SM_K1>>>(x, c1w, c1b, bng, bnb, bnm, bnv);
    k23_conv2_inv<<<dim3(8, 8, 8), 256, SM_K23>>>(x, c2w, c2b);
    k4_fused<<<256, 256, SM_K4>>>(p1w, p1b, lng, lnb, p2w, p2b, x, out);
}

// round 17
// speedup vs baseline: 1.3256x; 1.0566x over previous
#include <cuda_runtime.h>
#include <cuda_bf16.h>
#include <math.h>

// Problem constants
#define BB   8
#define DIM  128
#define HH   64
#define WW   64
#define HW   4096
#define KK   7
#define GG   8
#define GC   16
#define C1   32
#define C2   392
#define NPIX 32768

// -------- scratch (device globals) --------
__device__ unsigned g_tb[BB * 16 * HW];       // conv1+bn+relu, bf16 c-pairs [b][c2][px] (2 MB)
__device__ float    g_y[NPIX * DIM];          // involution out, NHWC fp32 (17 MB)

// -------- helpers --------
__device__ __forceinline__ unsigned packbf(float lo, float hi) {
    unsigned r; asm("cvt.rn.bf16x2.f32 %0, %1, %2;" : "=r"(r) : "f"(hi), "f"(lo)); return r;
}
__device__ __forceinline__ void mma16(float* c, unsigned a0, unsigned a1,
                                      unsigned a2, unsigned a3,
                                      unsigned b0, unsigned b1) {
    asm volatile(
        "mma.sync.aligned.m16n8k16.row.col.f32.bf16.bf16.f32 "
        "{%0,%1,%2,%3}, {%4,%5,%6,%7}, {%8,%9}, {%0,%1,%2,%3};\n"
        : "+f"(c[0]), "+f"(c[1]), "+f"(c[2]), "+f"(c[3])
        : "r"(a0), "r"(a1), "r"(a2), "r"(a3), "r"(b0), "r"(b1));
}
__device__ __forceinline__ void ldsm4(unsigned& r0, unsigned& r1,
                                      unsigned& r2, unsigned& r3, unsigned addr) {
    asm volatile("ldmatrix.sync.aligned.m8n8.x4.shared.b16 {%0,%1,%2,%3}, [%4];\n"
        : "=r"(r0), "=r"(r1), "=r"(r2), "=r"(r3) : "r"(addr));
}
__device__ __forceinline__ void cpasync16(unsigned dst, const void* src) {
    asm volatile("cp.async.cg.shared.global [%0], [%1], 16;\n" :: "r"(dst), "l"(src));
}
// tanh-form GELU (validated: rel_err unchanged at 1.79e-4)
__device__ __forceinline__ float gelu_fast(float z) {
    float u = z * (0.7978845608f + 0.0356774081f * z * z);
    float e = __expf(-2.f * u);
    return __fdividef(z, 1.f + e);
}

// ldmatrix operand row strides (u32 / bytes)
#define RS   68
#define RSB  272
#define RS2  132
#define RSB2 528

// =====================================================================
// K1: t = relu(bn(conv1(x)))  — bf16 MMA, M=32, N=128px, K=128.
// x staged fp32 via cp.async (16/thread, overlapped with weight staging),
// then smem→smem bf16 pack. Epilogue scratch reuses the fp32 region.
// smem: wAu[2176] | xsu[8704] | xf[16384 f32] | bs/ss  = 107 KB
// =====================================================================
__global__ __launch_bounds__(256) void k1_conv1(
    const float* __restrict__ x,  const float* __restrict__ w1,
    const float* __restrict__ b1, const float* __restrict__ bng,
    const float* __restrict__ bnb, const float* __restrict__ bnm,
    const float* __restrict__ bnv) {
    extern __shared__ unsigned smu[];
    unsigned* wAu = smu;                  // 32*68
    unsigned* xsu = smu + 2176;           // 64*136
    float* xf = (float*)(smu + 10880);    // 128*128 fp32
    float* bs = (float*)(smu + 27264);    // 32
    float* ss = bs + 32;                  // 32
    float* ts = xf;                       // epilogue scratch (32*132), unions xf
    int tid = threadIdx.x;
    int pb = blockIdx.x * 128, b = pb >> 12, pin = pb & 4095;
    const float* xb = x + b * DIM * HW + pin;

    // ---- fire-and-forget x tile (fp32, 16B chunks) ----
    unsigned xfb = (unsigned)__cvta_generic_to_shared(xf);
#pragma unroll
    for (int k = 0; k < 16; k++) {
        int i = tid + k * 256;
        int c = i >> 5, ch = i & 31;
        cpasync16(xfb + (c * 128 + ch * 4) * 4, xb + c * HW + ch * 4);
    }
    asm volatile("cp.async.commit_group;\n");

    if (tid < 32) {
        float sc = bng[tid] * rsqrtf(bnv[tid] + 1e-5f);
        ss[tid] = sc;
        bs[tid] = b1[tid] * sc + bnb[tid] - bnm[tid] * sc;
    }
    __syncthreads();   // ss visible (does not wait on cp.async)
    for (int i = tid; i < 32 * 64; i += 256) {
        int o = i >> 6, c2 = i & 63;
        float sc = ss[o];
        wAu[o * 68 + c2] = packbf(w1[o * 128 + 2 * c2] * sc, w1[o * 128 + 2 * c2 + 1] * sc);
    }
    asm volatile("cp.async.wait_group 0;\n");
    __syncthreads();

    // ---- smem→smem bf16 pack ----
#pragma unroll
    for (int k = 0; k < 32; k++) {
        int i = tid + k * 256;
        int c2 = i >> 7, p = i & 127;
        xsu[c2 * 136 + p] = packbf(xf[(2 * c2) * 128 + p], xf[(2 * c2 + 1) * 128 + p]);
    }
    __syncthreads();

    int wid = tid >> 5, lane = tid & 31, gid = lane >> 2, ctid = lane & 3;
    int m = wid & 1, ng = wid >> 1;
    int px0 = ng * 32;
    float acc[4][4];
#pragma unroll
    for (int a = 0; a < 4; a++)
#pragma unroll
        for (int q = 0; q < 4; q++) acc[a][q] = 0.f;

#pragma unroll
    for (int s = 0; s < 8; s++) {
        const unsigned* ap = wAu + (m * 16 + gid) * 68 + s * 8 + ctid;
        unsigned a0 = ap[0], a1 = ap[8 * 68], a2 = ap[4], a3 = ap[8 * 68 + 4];
#pragma unroll
        for (int nt = 0; nt < 4; nt++) {
            int pxn = px0 + nt * 8 + gid;
            unsigned b0 = xsu[(s * 8 + ctid) * 136 + pxn];
            unsigned b1v = xsu[(s * 8 + ctid + 4) * 136 + pxn];
            mma16(acc[nt], a0, a1, a2, a3, b0, b1v);
        }
    }
    // epilogue writes ts (=xf region; disjoint from xsu still being read)
    int o0 = m * 16 + gid;
    float b0v = bs[o0], b1v = bs[o0 + 8];
#pragma unroll
    for (int nt = 0; nt < 4; nt++) {
        int px = px0 + nt * 8 + 2 * ctid;
        *(float2*)(ts + o0 * 132 + px) =
            make_float2(fmaxf(acc[nt][0] + b0v, 0.f), fmaxf(acc[nt][1] + b0v, 0.f));
        *(float2*)(ts + (o0 + 8) * 132 + px) =
            make_float2(fmaxf(acc[nt][2] + b1v, 0.f), fmaxf(acc[nt][3] + b1v, 0.f));
    }
    __syncthreads();

    // pack c-pairs → g_tb [b][c2][px] (coalesced u32 stores)
    unsigned* tbo = g_tb + b * 16 * HW + pin;
#pragma unroll
    for (int k = 0; k < 8; k++) {
        int i = tid + k * 256;
        int c2 = i >> 7, p = i & 127;
        tbo[c2 * HW + p] = packbf(ts[(2 * c2) * 132 + p], ts[(2 * c2 + 1) * 132 + p]);
    }
}

// =====================================================================
// K23: fused conv2 + involution (R10 compute shape). t staged via
// cp.async (straight u32 copy from g_tb), drained just before MMA.
// =====================================================================
#define XS_ROW 72
#define XS_CH  (14 * 72)
#define WGT_S  520
__global__ __launch_bounds__(256) void k23_conv2_inv(
    const float* __restrict__ x, const float* __restrict__ w2,
    const float* __restrict__ b2) {
    extern __shared__ float smf[];
    float* wgt = smf;
    float* xs  = smf + 49 * WGT_S;
    unsigned* tsu = (unsigned*)xs;
    unsigned* wAu = tsu + 16 * WGT_S;
    float* bsm = (float*)(wAu + 64 * 20);
    int tid = threadIdx.x;
    int h0 = blockIdx.x * 8;
    int g  = blockIdx.y;
    int b  = blockIdx.z;

    // ---- cp.async t tile (16 rows × 512 u32, 16B chunks: 8/thread) ----
    {
        const unsigned* tbp = g_tb + b * 16 * HW + h0 * 64;
        unsigned tsb = (unsigned)__cvta_generic_to_shared(tsu);
#pragma unroll
        for (int k = 0; k < 8; k++) {
            int i = tid + k * 256;
            int c2 = i >> 7, ch = i & 127;
            cpasync16(tsb + (c2 * WGT_S + ch * 4) * 4, tbp + c2 * HW + ch * 4);
        }
        asm volatile("cp.async.commit_group;\n");
    }
    for (int i = tid; i < 64 * 16; i += 256) {
        int o = i >> 4, c2 = i & 15;
        float a0 = 0.f, a1 = 0.f;
        if (o < 49) {
            int go = g * 49 + o;
            a0 = w2[go * C1 + 2 * c2];
            a1 = w2[go * C1 + 2 * c2 + 1];
        }
        wAu[o * 20 + c2] = packbf(a0, a1);
    }
    if (tid < 64) bsm[tid] = (tid < 49) ? b2[g * 49 + tid] : 0.f;
    asm volatile("cp.async.wait_group 0;\n");
    __syncthreads();

    int wid = tid >> 5, lane = tid & 31, gid = lane >> 2, ctid = lane & 3;
    int m = wid & 3, ng = wid >> 2;
    int orow = m * 16 + gid;
    float bb0 = bsm[orow], bb1 = bsm[orow + 8];
#pragma unroll
    for (int nh = 0; nh < 2; nh++) {
        float acc[16][4];
#pragma unroll
        for (int nt = 0; nt < 16; nt++)
#pragma unroll
            for (int q = 0; q < 4; q++) acc[nt][q] = 0.f;
#pragma unroll
        for (int s = 0; s < 2; s++) {
            const unsigned* ap = wAu + orow * 20 + s * 8 + ctid;
            unsigned a0 = ap[0], a1 = ap[8 * 20], a2 = ap[4], a3 = ap[8 * 20 + 4];
#pragma unroll
            for (int nt = 0; nt < 16; nt++) {
                int pxn = nh * 256 + ng * 128 + nt * 8 + gid;
                unsigned b0 = tsu[(s * 8 + ctid) * WGT_S + pxn];
                unsigned b1v = tsu[(s * 8 + ctid + 4) * WGT_S + pxn];
                mma16(acc[nt], a0, a1, a2, a3, b0, b1v);
            }
        }
#pragma unroll
        for (int nt = 0; nt < 16; nt++) {
            int px = nh * 256 + ng * 128 + nt * 8 + 2 * ctid;
            if (orow < 49)
                *(float2*)(wgt + orow * WGT_S + px) =
                    make_float2(acc[nt][0] + bb0, acc[nt][1] + bb0);
            if (orow + 8 < 49)
                *(float2*)(wgt + (orow + 8) * WGT_S + px) =
                    make_float2(acc[nt][2] + bb1, acc[nt][3] + bb1);
        }
    }
    __syncthreads();

    for (int i = tid; i < GC * XS_CH; i += 256) xs[i] = 0.f;
    __syncthreads();
    const float* xg = x + (b * DIM + g * GC) * HW;
    for (int idx = tid; idx < GC * 14 * 64; idx += 256) {
        int gc = idx / (14 * 64);
        int rem = idx - gc * (14 * 64);
        int rr = rem >> 6, ww = rem & 63;
        int hh = h0 - 3 + rr;
        if (hh >= 0 && hh < HH)
            xs[gc * XS_CH + rr * XS_ROW + ww + 3] = xg[gc * HW + hh * WW + ww];
    }
    __syncthreads();

    int gcH = tid & 1;
    int pxq = tid >> 1;
    int r = pxq >> 4, w0 = (pxq & 15) * 4;
    float acc[8][4];
#pragma unroll
    for (int gc8 = 0; gc8 < 8; gc8++)
#pragma unroll
        for (int l = 0; l < 4; l++) acc[gc8][l] = 0.f;

    const float* wp = wgt + r * 64 + w0;
#pragma unroll
    for (int i = 0; i < KK; i++) {
        float4 wv[KK];
#pragma unroll
        for (int j = 0; j < KK; j++)
            wv[j] = *(const float4*)(wp + (i * KK + j) * WGT_S);
#pragma unroll
        for (int gc8 = 0; gc8 < 8; gc8++) {
            int gc = gcH * 8 + gc8;
            const float* xrow = xs + gc * XS_CH + (r + i) * XS_ROW + w0;
            float4 xa = *(const float4*)(xrow);
            float4 xb4 = *(const float4*)(xrow + 4);
            float4 xc = *(const float4*)(xrow + 8);
            float xw[12] = {xa.x, xa.y, xa.z, xa.w, xb4.x, xb4.y, xb4.z, xb4.w,
                            xc.x, xc.y, xc.z, xc.w};
#pragma unroll
            for (int j = 0; j < KK; j++) {
                acc[gc8][0] += wv[j].x * xw[j];
                acc[gc8][1] += wv[j].y * xw[j + 1];
                acc[gc8][2] += wv[j].z * xw[j + 2];
                acc[gc8][3] += wv[j].w * xw[j + 3];
            }
        }
    }
#pragma unroll
    for (int l = 0; l < 4; l++) {
        float* yo = g_y + (b * HW + (h0 + r) * WW + w0 + l) * DIM + g * GC + gcH * 8;
        *(float4*)(yo)     = make_float4(acc[0][l], acc[1][l], acc[2][l], acc[3][l]);
        *(float4*)(yo + 4) = make_float4(acc[4][l], acc[5][l], acc[6][l], acc[7][l]);
    }
}

// =====================================================================
// K4: fused LN + pw1 + GELU + pw2 + residual — permuted-K direct path
// (unchanged from R15/R16 best).
// =====================================================================
#define OFF_A 0
#define OFF_B 8704
#define OFF_C 17408
#define OFF_D 34304
#define OFF_P 51200
#define SMU_TOT 51840
__global__ __launch_bounds__(256, 1) void k4_fused(
    const float* __restrict__ p1w, const float* __restrict__ p1b,
    const float* __restrict__ lng_g, const float* __restrict__ lnb_g,
    const float* __restrict__ p2w, const float* __restrict__ p2b,
    const float* __restrict__ x,   float* __restrict__ out) {
    extern __shared__ unsigned smu[];
    unsigned* Aw  = smu + OFF_A;
    unsigned* bT  = smu + OFF_B;
    unsigned* hB  = smu + OFF_C;
    unsigned* w2T = smu + OFF_D;
    float* b1s = (float*)(smu + OFF_P);
    float* b2s = b1s + 256;
    float* lng = b2s + 128;
    float* lnb = lng + 128;
    float* outT2 = (float*)(smu + OFF_D);
    int tid = threadIdx.x;
    int pb = blockIdx.x * 128, b = pb >> 12, pin = pb & 4095;

#pragma unroll
    for (int k = 0; k < 32; k++) {
        int i = tid + k * 256;
        int f = i >> 6, c2 = i & 63;
        float2 wv = *(const float2*)(p1w + f * 128 + 2 * c2);
        Aw[f * RS + c2] = packbf(wv.x, wv.y);
    }
#pragma unroll 8
    for (int k = 0; k < 64; k++) {
        int i = tid + k * 256;
        int c = i >> 7, kp = i & 127;
        int hf = kp >> 6, loc = kp & 63;
        int f = hf * 128 + ((loc >> 3) << 4) + (loc & 7);
        float lo = p2w[c * 256 + f];
        float hi = p2w[c * 256 + f + 8];
        w2T[c * RS2 + kp] = packbf(lo, hi);
    }
    b1s[tid] = p1b[tid];
    if (tid < 128) {
        b2s[tid] = p2b[tid];
        lng[tid] = lng_g[tid];
        lnb[tid] = lnb_g[tid];
    }
    __syncthreads();

    {
        int p = tid >> 1, half = tid & 1;
        const float* yp = g_y + (pb + p) * DIM + half * 64;
        float4 v[16];
        float s = 0.f, q = 0.f;
#pragma unroll
        for (int i = 0; i < 16; i++) {
            v[i] = *(const float4*)(yp + i * 4);
            s += v[i].x + v[i].y + v[i].z + v[i].w;
            q += v[i].x*v[i].x + v[i].y*v[i].y + v[i].z*v[i].z + v[i].w*v[i].w;
        }
        s += __shfl_xor_sync(0xffffffffu, s, 1);
        q += __shfl_xor_sync(0xffffffffu, q, 1);
        float mu = s * (1.f / 128.f);
        float var = q * (1.f / 128.f) - mu * mu;
        float rs = rsqrtf(var + 1e-6f);
        unsigned* brow = bT + p * RS + half * 32;
#pragma unroll
        for (int i = 0; i < 16; i++) {
            int c = half * 64 + i * 4;
            float n0 = (v[i].x - mu) * rs * lng[c+0] + lnb[c+0];
            float n1 = (v[i].y - mu) * rs * lng[c+1] + lnb[c+1];
            float n2 = (v[i].z - mu) * rs * lng[c+2] + lnb[c+2];
            float n3 = (v[i].w - mu) * rs * lng[c+3] + lnb[c+3];
            brow[2 * i]     = packbf(n0, n1);
            brow[2 * i + 1] = packbf(n2, n3);
        }
    }
    __syncthreads();

    int wid = tid >> 5, lane = tid & 31, gid = lane >> 2, ctid = lane & 3;
    int m = wid & 3, ng = wid >> 2;
    unsigned aBase1 = (unsigned)__cvta_generic_to_shared(Aw)
                    + (m * 32 + (lane & 15)) * RSB + (lane & 16);
    unsigned bBase1 = (unsigned)__cvta_generic_to_shared(bT)
                    + (ng * 64 + (lane & 7) + ((lane & 16) >> 1)) * RSB
                    + ((lane & 8) << 1);

    for (int hf = 0; hf < 2; hf++) {
        if (hf == 1) {
            __syncthreads();
#pragma unroll
            for (int k = 0; k < 32; k++) {
                int i = tid + k * 256;
                int f = i >> 6, c2 = i & 63;
                float2 wv = *(const float2*)(p1w + (128 + f) * 128 + 2 * c2);
                Aw[f * RS + c2] = packbf(wv.x, wv.y);
            }
            __syncthreads();
        }
        float acc[2][8][4];
#pragma unroll
        for (int mt = 0; mt < 2; mt++)
#pragma unroll
            for (int nt = 0; nt < 8; nt++)
#pragma unroll
                for (int q = 0; q < 4; q++) acc[mt][nt][q] = 0.f;
#pragma unroll
        for (int s = 0; s < 8; s++) {
            unsigned a[2][4];
#pragma unroll
            for (int mt = 0; mt < 2; mt++)
                ldsm4(a[mt][0], a[mt][1], a[mt][2], a[mt][3],
                      aBase1 + mt * 16 * RSB + s * 32);
#pragma unroll
            for (int ntp = 0; ntp < 4; ntp++) {
                unsigned b0, b1v, b2v, b3;
                ldsm4(b0, b1v, b2v, b3, bBase1 + ntp * 16 * RSB + s * 32);
#pragma unroll
                for (int mt = 0; mt < 2; mt++) {
                    mma16(acc[mt][2 * ntp],     a[mt][0], a[mt][1], a[mt][2], a[mt][3], b0, b1v);
                    mma16(acc[mt][2 * ntp + 1], a[mt][0], a[mt][1], a[mt][2], a[mt][3], b2v, b3);
                }
            }
        }
#pragma unroll
        for (int mt = 0; mt < 2; mt++) {
            int frow = m * 32 + mt * 16 + gid;
            int kp = hf * 64 + ((frow >> 4) << 3) + (frow & 7);
            float bb0 = b1s[hf * 128 + frow];
            float bb1 = b1s[hf * 128 + frow + 8];
#pragma unroll
            for (int nt = 0; nt < 8; nt++) {
                int px = ng * 64 + nt * 8 + 2 * ctid;
                hB[px * RS2 + kp] =
                    packbf(gelu_fast(acc[mt][nt][0] + bb0),
                           gelu_fast(acc[mt][nt][2] + bb1));
                hB[(px + 1) * RS2 + kp] =
                    packbf(gelu_fast(acc[mt][nt][1] + bb0),
                           gelu_fast(acc[mt][nt][3] + bb1));
            }
        }
    }
    __syncthreads();

    unsigned aBase2 = (unsigned)__cvta_generic_to_shared(w2T)
                    + (m * 32 + (lane & 15)) * RSB2 + (lane & 16);
    unsigned bBase2 = (unsigned)__cvta_generic_to_shared(hB)
                    + (ng * 64 + (lane & 7) + ((lane & 16) >> 1)) * RSB2
                    + ((lane & 8) << 1);
    float acc2[2][8][4];
#pragma unroll
    for (int mt = 0; mt < 2; mt++)
#pragma unroll
        for (int nt = 0; nt < 8; nt++)
#pragma unroll
            for (int q = 0; q < 4; q++) acc2[mt][nt][q] = 0.f;
#pragma unroll
    for (int s = 0; s < 16; s++) {
        unsigned a[2][4];
#pragma unroll
        for (int mt = 0; mt < 2; mt++)
            ldsm4(a[mt][0], a[mt][1], a[mt][2], a[mt][3],
                  aBase2 + mt * 16 * RSB2 + s * 32);
#pragma unroll
        for (int ntp = 0; ntp < 4; ntp++) {
            unsigned b0, b1v, b2v, b3;
            ldsm4(b0, b1v, b2v, b3, bBase2 + ntp * 16 * RSB2 + s * 32);
#pragma unroll
            for (int mt = 0; mt < 2; mt++) {
                mma16(acc2[mt][2 * ntp],     a[mt][0], a[mt][1], a[mt][2], a[mt][3], b0, b1v);
                mma16(acc2[mt][2 * ntp + 1], a[mt][0], a[mt][1], a[mt][2], a[mt][3], b2v, b3);
            }
        }
    }
    __syncthreads();

#pragma unroll
    for (int mt = 0; mt < 2; mt++) {
        int crow = m * 32 + mt * 16 + gid;
        float bb0 = b2s[crow], bb1 = b2s[crow + 8];
#pragma unroll
        for (int nt = 0; nt < 8; nt++) {
            int px = ng * 64 + nt * 8 + 2 * ctid;
            *(float2*)(outT2 + crow * 130 + px) =
                make_float2(acc2[mt][nt][0] + bb0, acc2[mt][nt][1] + bb0);
            *(float2*)(outT2 + (crow + 8) * 130 + px) =
                make_float2(acc2[mt][nt][2] + bb1, acc2[mt][nt][3] + bb1);
        }
    }
    __syncthreads();

#pragma unroll
    for (int k = 0; k < 32; k++) {
        int i = tid + k * 256;
        int c = i >> 6, p2 = (i & 63) * 2;
        float2 v = *(const float2*)(outT2 + c * 130 + p2);
        int base = (b * DIM + c) * HW + pin + p2;
        float2 xi = *(const float2*)(x + base);
        *(float2*)(out + base) = make_float2(v.x + xi.x, v.y + xi.y);
    }
}

// =====================================================================
extern "C" void kernel_launch(void* const* d_in, const int* in_sizes, int n_in,
                              void* d_out, int out_size) {
    const float* x    = (const float*)d_in[0];
    const float* c1w  = (const float*)d_in[1];
    const float* c1b  = (const float*)d_in[2];
    const float* bng  = (const float*)d_in[3];
    const float* bnb  = (const float*)d_in[4];
    const float* bnm  = (const float*)d_in[5];
    const float* bnv  = (const float*)d_in[6];
    const float* c2w  = (const float*)d_in[7];
    const float* c2b  = (const float*)d_in[8];
    const float* lng  = (const float*)d_in[9];
    const float* lnb  = (const float*)d_in[10];
    const float* p1w  = (const float*)d_in[11];
    const float* p1b  = (const float*)d_in[12];
    const float* p2w  = (const float*)d_in[13];
    const float* p2b  = (const float*)d_in[14];
    float* out = (float*)d_out;

    const int SM_K1  = 27328 * 4;                         // 109312
    const int SM_K23 = (49 * WGT_S + GC * XS_CH) * 4;     // 166432
    const int SM_K4  = SMU_TOT * 4;                       // 207360

    cudaFuncSetAttribute(k1_conv1,      cudaFuncAttributeMaxDynamicSharedMemorySize, SM_K1);
    cudaFuncSetAttribute(k23_conv2_inv, cudaFuncAttributeMaxDynamicSharedMemorySize, SM_K23);
    cudaFuncSetAttribute(k4_fused,      cudaFuncAttributeMaxDynamicSharedMemorySize, SM_K4);

    k1_conv1<<<256, 256, SM_K1>>>(x, c1w, c1b, bng, bnb, bnm, bnv);
    k23_conv2_inv<<<dim3(8, 8, 8), 256, SM_K23>>>(x, c2w, c2b);
    k4_fused<<<256, 256, SM_K4>>>(p1w, p1b, lng, lnb, p2w, p2b, x, out);
}